// round 1
// baseline (speedup 1.0000x reference)
#include <cuda_runtime.h>
#include <cstdint>
#include <cstddef>

#define NN 170000
#define NE 1200000

// ---------------- device scratch (allocation-free) ----------------
__device__ float g_G[(size_t)NN * 128];    // transformed features (pre-aggregation)
__device__ float g_AGG[(size_t)NN * 128];  // aggregation accumulator
__device__ int   g_deg_out[NN];
__device__ int   g_deg_in[NN];
__device__ float g_norm_out[NN];
__device__ float g_norm_in[NN];

// ---------------- degree / norm kernels ----------------
__global__ void zero_deg_kernel() {
    int i = blockIdx.x * blockDim.x + threadIdx.x;
    if (i < NN) { g_deg_out[i] = 0; g_deg_in[i] = 0; }
}

__global__ void count_deg_kernel(const int* __restrict__ src, const int* __restrict__ dst) {
    int e = blockIdx.x * blockDim.x + threadIdx.x;
    if (e < NE) {
        atomicAdd(&g_deg_out[src[e]], 1);
        atomicAdd(&g_deg_in[dst[e]], 1);
    }
}

__global__ void norm_kernel() {
    int i = blockIdx.x * blockDim.x + threadIdx.x;
    if (i < NN) {
        int dout = g_deg_out[i]; if (dout < 1) dout = 1;
        int din  = g_deg_in[i];  if (din  < 1) din  = 1;
        g_norm_out[i] = rsqrtf((float)dout);
        g_norm_in[i]  = rsqrtf((float)din);
    }
}

__global__ void zero_agg_kernel(int n4) {
    int i = blockIdx.x * blockDim.x + threadIdx.x;
    if (i < n4) reinterpret_cast<float4*>(g_AGG)[i] = make_float4(0.f, 0.f, 0.f, 0.f);
}

// ---------------- GEMM: G = f(X) @ W ----------------
// FUSE=false: a[i][k] = X[i][k] * norm_out[i]                       (layer 0, X=feat)
// FUSE=true : a[i][k] = relu(AGG[i][k]*norm_in[i] + bias_prev[k]) * norm_out[i]
// Each block: loads W (128 x OUTD) into shared once, streams 32-row A tiles.
// 8 warps; warp w computes rows 4w..4w+3; lane covers OUTD/32 contiguous cols.
template <int OUTD, bool FUSE>
__global__ void __launch_bounds__(256) gemm_kernel(const float* __restrict__ X,
                                                   const float* __restrict__ W,
                                                   const float* __restrict__ bias_prev) {
    constexpr int CPT = OUTD / 32;       // cols per thread (4 or 2)
    constexpr int AROW = 136;            // padded A row stride (544B, 16B aligned)
    extern __shared__ float smem[];
    float* Wsh = smem;                   // 128 * OUTD
    float* Ash = smem + 128 * OUTD;      // 32 * AROW

    const int tid  = threadIdx.x;
    const int lane = tid & 31;
    const int warp = tid >> 5;

    for (int i = tid; i < 128 * OUTD / 4; i += 256)
        reinterpret_cast<float4*>(Wsh)[i] = reinterpret_cast<const float4*>(W)[i];

    const int ntiles = (NN + 31) / 32;
    for (int tile = blockIdx.x; tile < ntiles; tile += gridDim.x) {
        __syncthreads();   // protect Ash from previous iteration's readers
        const int rowbase = tile * 32;

        // load + transform 32x128 A tile (each thread: 4 float4s)
        for (int i = tid; i < 32 * 32; i += 256) {
            const int r   = i >> 5;
            const int c4  = i & 31;
            const int row = rowbase + r;
            float4 v = make_float4(0.f, 0.f, 0.f, 0.f);
            if (row < NN) {
                const float no = g_norm_out[row];
                if (FUSE) {
                    v = reinterpret_cast<const float4*>(g_AGG + (size_t)row * 128)[c4];
                    const float  ni = g_norm_in[row];
                    const float4 bb = reinterpret_cast<const float4*>(bias_prev)[c4];
                    v.x = fmaxf(fmaf(v.x, ni, bb.x), 0.f) * no;
                    v.y = fmaxf(fmaf(v.y, ni, bb.y), 0.f) * no;
                    v.z = fmaxf(fmaf(v.z, ni, bb.z), 0.f) * no;
                    v.w = fmaxf(fmaf(v.w, ni, bb.w), 0.f) * no;
                } else {
                    v = reinterpret_cast<const float4*>(X + (size_t)row * 128)[c4];
                    v.x *= no; v.y *= no; v.z *= no; v.w *= no;
                }
            }
            reinterpret_cast<float4*>(&Ash[r * AROW])[c4] = v;
        }
        __syncthreads();

        float acc[4][CPT] = {};
        const int r0 = warp * 4;
        const float* a0p = &Ash[(r0 + 0) * AROW];
        const float* a1p = &Ash[(r0 + 1) * AROW];
        const float* a2p = &Ash[(r0 + 2) * AROW];
        const float* a3p = &Ash[(r0 + 3) * AROW];

#pragma unroll 8
        for (int k = 0; k < 128; k++) {
            const float a0 = a0p[k], a1 = a1p[k], a2 = a2p[k], a3 = a3p[k];
            if constexpr (CPT == 4) {
                const float4 wv = reinterpret_cast<const float4*>(&Wsh[k * OUTD])[lane];
                acc[0][0] += a0 * wv.x; acc[0][1] += a0 * wv.y; acc[0][2] += a0 * wv.z; acc[0][3] += a0 * wv.w;
                acc[1][0] += a1 * wv.x; acc[1][1] += a1 * wv.y; acc[1][2] += a1 * wv.z; acc[1][3] += a1 * wv.w;
                acc[2][0] += a2 * wv.x; acc[2][1] += a2 * wv.y; acc[2][2] += a2 * wv.z; acc[2][3] += a2 * wv.w;
                acc[3][0] += a3 * wv.x; acc[3][1] += a3 * wv.y; acc[3][2] += a3 * wv.z; acc[3][3] += a3 * wv.w;
            } else {
                const float2 wv = reinterpret_cast<const float2*>(&Wsh[k * OUTD])[lane];
                acc[0][0] += a0 * wv.x; acc[0][1] += a0 * wv.y;
                acc[1][0] += a1 * wv.x; acc[1][1] += a1 * wv.y;
                acc[2][0] += a2 * wv.x; acc[2][1] += a2 * wv.y;
                acc[3][0] += a3 * wv.x; acc[3][1] += a3 * wv.y;
            }
        }

#pragma unroll
        for (int r = 0; r < 4; r++) {
            const int row = rowbase + r0 + r;
            if (row < NN) {
                if constexpr (CPT == 4) {
                    float4 o = make_float4(acc[r][0], acc[r][1], acc[r][2], acc[r][3]);
                    reinterpret_cast<float4*>(g_G + (size_t)row * OUTD)[lane] = o;
                } else {
                    float2 o = make_float2(acc[r][0], acc[r][1]);
                    reinterpret_cast<float2*>(g_G + (size_t)row * OUTD)[lane] = o;
                }
            }
        }
    }
}

// ---------------- edge scatter: AGG[dst] += G[src] ----------------
__device__ __forceinline__ void red_add_v4(float* p, float4 v) {
#if defined(__CUDA_ARCH__) && (__CUDA_ARCH__ >= 900)
    asm volatile("red.global.add.v4.f32 [%0], {%1,%2,%3,%4};"
                 :: "l"(p), "f"(v.x), "f"(v.y), "f"(v.z), "f"(v.w) : "memory");
#else
    atomicAdd(p + 0, v.x); atomicAdd(p + 1, v.y);
    atomicAdd(p + 2, v.z); atomicAdd(p + 3, v.w);
#endif
}

template <int WIDTH>
__global__ void scatter_kernel(const int* __restrict__ src, const int* __restrict__ dst) {
    constexpr int C4 = WIDTH / 4;
    constexpr int SH = (WIDTH == 128) ? 5 : 4;
    const long long t = (long long)blockIdx.x * blockDim.x + threadIdx.x;
    const int e = (int)(t >> SH);
    if (e >= NE) return;
    const int c = (int)t & (C4 - 1);
    const int s = __ldg(src + e);   // intra-warp broadcast: 1 wavefront
    const int d = __ldg(dst + e);
    const float4 v = reinterpret_cast<const float4*>(g_G + (size_t)s * WIDTH)[c];
    red_add_v4(g_AGG + (size_t)d * WIDTH + (size_t)c * 4, v);
}

// ---------------- final pointwise: out = AGG*norm_in + b2 ----------------
__global__ void final_kernel(const float* __restrict__ b2, float* __restrict__ out) {
    const int n4 = NN * 16;  // 64 floats per row = 16 float4
    int i = blockIdx.x * blockDim.x + threadIdx.x;
    if (i >= n4) return;
    const int row = i >> 4;
    const int c4  = i & 15;
    float4 v = reinterpret_cast<const float4*>(g_AGG)[i];
    const float  ni = g_norm_in[row];
    const float4 bb = reinterpret_cast<const float4*>(b2)[c4];
    float4 o;
    o.x = fmaf(v.x, ni, bb.x);
    o.y = fmaf(v.y, ni, bb.y);
    o.z = fmaf(v.z, ni, bb.z);
    o.w = fmaf(v.w, ni, bb.w);
    reinterpret_cast<float4*>(out)[i] = o;
}

// ---------------- launch ----------------
extern "C" void kernel_launch(void* const* d_in, const int* in_sizes, int n_in,
                              void* d_out, int out_size) {
    const float* feat = (const float*)d_in[0];
    const int*   src  = (const int*)d_in[1];
    const int*   dst  = (const int*)d_in[2];
    const float* W0   = (const float*)d_in[3];
    const float* b0   = (const float*)d_in[4];
    const float* W1   = (const float*)d_in[5];
    const float* b1   = (const float*)d_in[6];
    const float* W2   = (const float*)d_in[7];
    const float* b2   = (const float*)d_in[8];
    float* out = (float*)d_out;

    const int SM128 = 128 * 128 * 4 + 32 * 136 * 4;  // 82944 B
    const int SM64  = 128 * 64  * 4 + 32 * 136 * 4;  // 50176 B
    cudaFuncSetAttribute(gemm_kernel<128, false>, cudaFuncAttributeMaxDynamicSharedMemorySize, SM128);
    cudaFuncSetAttribute(gemm_kernel<128, true>,  cudaFuncAttributeMaxDynamicSharedMemorySize, SM128);
    cudaFuncSetAttribute(gemm_kernel<64,  true>,  cudaFuncAttributeMaxDynamicSharedMemorySize, SM64);

    const int GGRID = 296;  // 2 blocks/SM (82944B smem each)
    const int TPB = 256;

    // degrees + norms
    zero_deg_kernel<<<(NN + TPB - 1) / TPB, TPB>>>();
    count_deg_kernel<<<(NE + TPB - 1) / TPB, TPB>>>(src, dst);
    norm_kernel<<<(NN + TPB - 1) / TPB, TPB>>>();

    // layer 0: G = (feat*norm_out) @ W0 ; AGG = scatter(G)
    gemm_kernel<128, false><<<GGRID, TPB, SM128>>>(feat, W0, nullptr);
    zero_agg_kernel<<<(NN * 32 + TPB - 1) / TPB, TPB>>>(NN * 32);
    {
        long long tot = (long long)NE * 32;
        scatter_kernel<128><<<(int)((tot + TPB - 1) / TPB), TPB>>>(src, dst);
    }

    // layer 1: G = (relu(AGG*norm_in + b0)*norm_out) @ W1 ; AGG = scatter(G)
    gemm_kernel<128, true><<<GGRID, TPB, SM128>>>(nullptr, W1, b0);
    zero_agg_kernel<<<(NN * 32 + TPB - 1) / TPB, TPB>>>(NN * 32);
    {
        long long tot = (long long)NE * 32;
        scatter_kernel<128><<<(int)((tot + TPB - 1) / TPB), TPB>>>(src, dst);
    }

    // layer 2 (64-wide): G = (relu(AGG*norm_in + b1)*norm_out) @ W2 ; AGG = scatter(G)
    gemm_kernel<64, true><<<GGRID, TPB, SM64>>>(nullptr, W2, b1);
    zero_agg_kernel<<<(NN * 16 + TPB - 1) / TPB, TPB>>>(NN * 16);
    {
        long long tot = (long long)NE * 16;
        scatter_kernel<64><<<(int)((tot + TPB - 1) / TPB), TPB>>>(src, dst);
    }

    // out = AGG*norm_in + b2
    final_kernel<<<(NN * 16 + TPB - 1) / TPB, TPB>>>(b2, out);
}

// round 2
// speedup vs baseline: 1.0514x; 1.0514x over previous
#include <cuda_runtime.h>
#include <cstdint>
#include <cstddef>

#define NN 170000
#define NE 1200000

// ---------------- device scratch (allocation-free) ----------------
__device__ float g_G[(size_t)NN * 128];    // transformed features (pre-aggregation)
__device__ float g_AGG[(size_t)NN * 128];  // aggregation accumulator
__device__ int   g_deg_out[NN];
__device__ int   g_deg_in[NN];
__device__ float g_norm_out[NN];
__device__ float g_norm_in[NN];

// ---------------- degree / norm kernels ----------------
__global__ void zero_deg_kernel() {
    int i = blockIdx.x * blockDim.x + threadIdx.x;
    if (i < NN) { g_deg_out[i] = 0; g_deg_in[i] = 0; }
}

__global__ void count_deg_kernel(const int* __restrict__ src, const int* __restrict__ dst) {
    int e = blockIdx.x * blockDim.x + threadIdx.x;
    if (e < NE) {
        atomicAdd(&g_deg_out[src[e]], 1);
        atomicAdd(&g_deg_in[dst[e]], 1);
    }
}

__global__ void norm_kernel() {
    int i = blockIdx.x * blockDim.x + threadIdx.x;
    if (i < NN) {
        int dout = g_deg_out[i]; if (dout < 1) dout = 1;
        int din  = g_deg_in[i];  if (din  < 1) din  = 1;
        g_norm_out[i] = rsqrtf((float)dout);
        g_norm_in[i]  = rsqrtf((float)din);
    }
}

__global__ void zero_agg_kernel(int n4) {
    int i = blockIdx.x * blockDim.x + threadIdx.x;
    if (i < n4) reinterpret_cast<float4*>(g_AGG)[i] = make_float4(0.f, 0.f, 0.f, 0.f);
}

// ---------------- tf32 helpers ----------------
__device__ __forceinline__ void split_tf32(float v, float& hi, float& lo) {
    uint32_t hb; asm("cvt.rna.tf32.f32 %0, %1;" : "=r"(hb) : "f"(v));
    hi = __uint_as_float(hb);
    float r = v - hi;
    uint32_t lb; asm("cvt.rna.tf32.f32 %0, %1;" : "=r"(lb) : "f"(r));
    lo = __uint_as_float(lb);
}

__device__ __forceinline__ void mma_tf32(float* c, const uint32_t* a, uint32_t b0, uint32_t b1) {
    asm volatile(
        "mma.sync.aligned.m16n8k8.row.col.f32.tf32.tf32.f32 "
        "{%0,%1,%2,%3}, {%4,%5,%6,%7}, {%8,%9}, {%0,%1,%2,%3};"
        : "+f"(c[0]), "+f"(c[1]), "+f"(c[2]), "+f"(c[3])
        : "r"(a[0]), "r"(a[1]), "r"(a[2]), "r"(a[3]), "r"(b0), "r"(b1));
}

// ---------------- tensor-core GEMM (3xTF32 compensated): G = f(X) @ W ----------------
// FUSE=false: a[i][k] = X[i][k] * norm_out[i]
// FUSE=true : a[i][k] = relu(AGG[i][k]*norm_in[i] + bias_prev[k]) * norm_out[i]
// Persistent blocks; W(hi,lo) resident in smem transposed [n][k], A tiles of 64 rows.
// Warp grid 2(M) x 4(N). Stride 132 => (4*row + k) mod 32 unique => conflict-free LDS.
template <int OUTD, bool FUSE>
__global__ void __launch_bounds__(256) mma_gemm(const float* __restrict__ X,
                                                const float* __restrict__ W,
                                                const float* __restrict__ bias_prev) {
    constexpr int NF = OUTD / 32;   // n-frags per warp
    constexpr int P  = 132;
    extern __shared__ float smem[];
    float* Wh = smem;               // [OUTD][P]
    float* Wl = Wh + OUTD * P;
    float* Ah = Wl + OUTD * P;      // [64][P]
    float* Al = Ah + 64 * P;

    const int tid  = threadIdx.x;
    const int lane = tid & 31;
    const int warp = tid >> 5;
    const int mw   = warp & 1;      // 0..1
    const int nw   = warp >> 1;     // 0..3

    // Load + split W into smem, transposed [n][k]
    for (int i = tid; i < 128 * OUTD; i += 256) {
        const int k = i / OUTD, n = i - k * OUTD;
        float hi, lo;
        split_tf32(W[i], hi, lo);
        Wh[n * P + k] = hi;
        Wl[n * P + k] = lo;
    }

    const int ntiles = (NN + 63) / 64;
    for (int tile = blockIdx.x; tile < ntiles; tile += gridDim.x) {
        __syncthreads();  // W visible (1st iter); protect Ash readers (later iters)
        const int rowbase = tile * 64;

        // Build A tile: 64 rows x 128 cols, fused transform + tf32 split
        for (int i = tid; i < 64 * 32; i += 256) {
            const int r = i >> 5, c4 = i & 31;
            const int row = rowbase + r;
            float4 v = make_float4(0.f, 0.f, 0.f, 0.f);
            if (row < NN) {
                const float no = g_norm_out[row];
                if (FUSE) {
                    v = reinterpret_cast<const float4*>(g_AGG + (size_t)row * 128)[c4];
                    const float  ni = g_norm_in[row];
                    const float4 bb = reinterpret_cast<const float4*>(bias_prev)[c4];
                    v.x = fmaxf(fmaf(v.x, ni, bb.x), 0.f) * no;
                    v.y = fmaxf(fmaf(v.y, ni, bb.y), 0.f) * no;
                    v.z = fmaxf(fmaf(v.z, ni, bb.z), 0.f) * no;
                    v.w = fmaxf(fmaf(v.w, ni, bb.w), 0.f) * no;
                } else {
                    v = reinterpret_cast<const float4*>(X + (size_t)row * 128)[c4];
                    v.x *= no; v.y *= no; v.z *= no; v.w *= no;
                }
            }
            float4 h4, l4;
            split_tf32(v.x, h4.x, l4.x);
            split_tf32(v.y, h4.y, l4.y);
            split_tf32(v.z, h4.z, l4.z);
            split_tf32(v.w, h4.w, l4.w);
            *reinterpret_cast<float4*>(&Ah[r * P + c4 * 4]) = h4;  // r*132 is 16B-aligned
            *reinterpret_cast<float4*>(&Al[r * P + c4 * 4]) = l4;
        }
        __syncthreads();

        float acc[2][NF][4];
#pragma unroll
        for (int mf = 0; mf < 2; mf++)
#pragma unroll
            for (int nf = 0; nf < NF; nf++)
#pragma unroll
                for (int j = 0; j < 4; j++) acc[mf][nf][j] = 0.f;

        const int rA = mw * 32 + (lane >> 2);
#pragma unroll 4
        for (int kk = 0; kk < 16; kk++) {
            const int k0 = kk * 8 + (lane & 3);
            uint32_t ah[2][4], al[2][4];
#pragma unroll
            for (int mf = 0; mf < 2; mf++) {
                const int r = rA + mf * 16;
                ah[mf][0] = __float_as_uint(Ah[r * P + k0]);
                ah[mf][1] = __float_as_uint(Ah[(r + 8) * P + k0]);
                ah[mf][2] = __float_as_uint(Ah[r * P + k0 + 4]);
                ah[mf][3] = __float_as_uint(Ah[(r + 8) * P + k0 + 4]);
                al[mf][0] = __float_as_uint(Al[r * P + k0]);
                al[mf][1] = __float_as_uint(Al[(r + 8) * P + k0]);
                al[mf][2] = __float_as_uint(Al[r * P + k0 + 4]);
                al[mf][3] = __float_as_uint(Al[(r + 8) * P + k0 + 4]);
            }
#pragma unroll
            for (int nf = 0; nf < NF; nf++) {
                const int n = nw * (NF * 8) + nf * 8 + (lane >> 2);
                const uint32_t bh0 = __float_as_uint(Wh[n * P + k0]);
                const uint32_t bh1 = __float_as_uint(Wh[n * P + k0 + 4]);
                const uint32_t bl0 = __float_as_uint(Wl[n * P + k0]);
                const uint32_t bl1 = __float_as_uint(Wl[n * P + k0 + 4]);
#pragma unroll
                for (int mf = 0; mf < 2; mf++) {
                    mma_tf32(acc[mf][nf], ah[mf], bh0, bh1);  // hi*hi
                    mma_tf32(acc[mf][nf], ah[mf], bl0, bl1);  // hi*lo
                    mma_tf32(acc[mf][nf], al[mf], bh0, bh1);  // lo*hi
                }
            }
        }

        // Store C
#pragma unroll
        for (int mf = 0; mf < 2; mf++) {
            const int r0 = rowbase + mw * 32 + mf * 16 + (lane >> 2);
#pragma unroll
            for (int nf = 0; nf < NF; nf++) {
                const int col = nw * (NF * 8) + nf * 8 + (lane & 3) * 2;
                if (r0 < NN)
                    *reinterpret_cast<float2*>(&g_G[(size_t)r0 * OUTD + col]) =
                        make_float2(acc[mf][nf][0], acc[mf][nf][1]);
                if (r0 + 8 < NN)
                    *reinterpret_cast<float2*>(&g_G[(size_t)(r0 + 8) * OUTD + col]) =
                        make_float2(acc[mf][nf][2], acc[mf][nf][3]);
            }
        }
    }
}

// ---------------- edge scatter: AGG[dst] += G[src] ----------------
__device__ __forceinline__ void red_add_v4(float* p, float4 v) {
    asm volatile("red.global.add.v4.f32 [%0], {%1,%2,%3,%4};"
                 :: "l"(p), "f"(v.x), "f"(v.y), "f"(v.z), "f"(v.w) : "memory");
}

template <int WIDTH>
__global__ void scatter_kernel(const int* __restrict__ src, const int* __restrict__ dst) {
    constexpr int C4 = WIDTH / 4;
    constexpr int SH = (WIDTH == 128) ? 5 : 4;
    const long long t = (long long)blockIdx.x * blockDim.x + threadIdx.x;
    const int e = (int)(t >> SH);
    if (e >= NE) return;
    const int c = (int)t & (C4 - 1);
    const int s = __ldg(src + e);
    const int d = __ldg(dst + e);
    const float4 v = reinterpret_cast<const float4*>(g_G + (size_t)s * WIDTH)[c];
    red_add_v4(g_AGG + (size_t)d * WIDTH + (size_t)c * 4, v);
}

// ---------------- final pointwise: out = AGG*norm_in + b2 ----------------
__global__ void final_kernel(const float* __restrict__ b2, float* __restrict__ out) {
    const int n4 = NN * 16;
    int i = blockIdx.x * blockDim.x + threadIdx.x;
    if (i >= n4) return;
    const int row = i >> 4;
    const int c4  = i & 15;
    float4 v = reinterpret_cast<const float4*>(g_AGG)[i];
    const float  ni = g_norm_in[row];
    const float4 bb = reinterpret_cast<const float4*>(b2)[c4];
    float4 o;
    o.x = fmaf(v.x, ni, bb.x);
    o.y = fmaf(v.y, ni, bb.y);
    o.z = fmaf(v.z, ni, bb.z);
    o.w = fmaf(v.w, ni, bb.w);
    reinterpret_cast<float4*>(out)[i] = o;
}

// ---------------- launch ----------------
extern "C" void kernel_launch(void* const* d_in, const int* in_sizes, int n_in,
                              void* d_out, int out_size) {
    const float* feat = (const float*)d_in[0];
    const int*   src  = (const int*)d_in[1];
    const int*   dst  = (const int*)d_in[2];
    const float* W0   = (const float*)d_in[3];
    const float* b0   = (const float*)d_in[4];
    const float* W1   = (const float*)d_in[5];
    const float* b1   = (const float*)d_in[6];
    const float* W2   = (const float*)d_in[7];
    const float* b2   = (const float*)d_in[8];
    float* out = (float*)d_out;

    const int SM128 = (2 * 128 * 132 + 2 * 64 * 132) * 4;  // 202752 B
    const int SM64  = (2 * 64 * 132 + 2 * 64 * 132) * 4;   // 135168 B
    cudaFuncSetAttribute(mma_gemm<128, false>, cudaFuncAttributeMaxDynamicSharedMemorySize, SM128);
    cudaFuncSetAttribute(mma_gemm<128, true>,  cudaFuncAttributeMaxDynamicSharedMemorySize, SM128);
    cudaFuncSetAttribute(mma_gemm<64,  true>,  cudaFuncAttributeMaxDynamicSharedMemorySize, SM64);

    const int GGRID = 148;  // persistent: 1 block/SM (smem-bound)
    const int TPB = 256;

    // degrees + norms
    zero_deg_kernel<<<(NN + TPB - 1) / TPB, TPB>>>();
    count_deg_kernel<<<(NE + TPB - 1) / TPB, TPB>>>(src, dst);
    norm_kernel<<<(NN + TPB - 1) / TPB, TPB>>>();

    // layer 0
    mma_gemm<128, false><<<GGRID, TPB, SM128>>>(feat, W0, nullptr);
    zero_agg_kernel<<<(NN * 32 + TPB - 1) / TPB, TPB>>>(NN * 32);
    {
        long long tot = (long long)NE * 32;
        scatter_kernel<128><<<(int)((tot + TPB - 1) / TPB), TPB>>>(src, dst);
    }

    // layer 1
    mma_gemm<128, true><<<GGRID, TPB, SM128>>>(nullptr, W1, b0);
    zero_agg_kernel<<<(NN * 32 + TPB - 1) / TPB, TPB>>>(NN * 32);
    {
        long long tot = (long long)NE * 32;
        scatter_kernel<128><<<(int)((tot + TPB - 1) / TPB), TPB>>>(src, dst);
    }

    // layer 2 (64-wide)
    mma_gemm<64, true><<<GGRID, TPB, SM64>>>(nullptr, W2, b1);
    zero_agg_kernel<<<(NN * 16 + TPB - 1) / TPB, TPB>>>(NN * 16);
    {
        long long tot = (long long)NE * 16;
        scatter_kernel<64><<<(int)((tot + TPB - 1) / TPB), TPB>>>(src, dst);
    }

    // out = AGG*norm_in + b2
    final_kernel<<<(NN * 16 + TPB - 1) / TPB, TPB>>>(b2, out);
}

// round 4
// speedup vs baseline: 1.6206x; 1.5413x over previous
#include <cuda_runtime.h>
#include <cstdint>
#include <cstddef>

#define NN 170000
#define NE 1200000
#define NBLK_SCAN 167   // ceil(NN / 1024)

// ---------------- device scratch (allocation-free) ----------------
__device__ float g_G[(size_t)NN * 128];   // GEMM output (pre-aggregation)
__device__ float g_H[(size_t)NN * 128];   // post-aggregation, post-transform features
__device__ int   g_deg_out[NN];
__device__ int   g_cnt[NN];               // in-degree counts
__device__ int   g_off[NN];               // CSR row offsets (exclusive)
__device__ int   g_fill[NN];
__device__ int   g_bsum[NBLK_SCAN];
__device__ float g_norm_out[NN];
__device__ float g_norm_in[NN];
__device__ int   g_csr_src[NE];

// ---------------- CSR build ----------------
__global__ void zero_kernel() {
    int i = blockIdx.x * blockDim.x + threadIdx.x;
    if (i < NN) { g_deg_out[i] = 0; g_cnt[i] = 0; g_fill[i] = 0; }
}

__global__ void hist_kernel(const int* __restrict__ src, const int* __restrict__ dst) {
    int e = blockIdx.x * blockDim.x + threadIdx.x;
    if (e < NE) {
        atomicAdd(&g_deg_out[src[e]], 1);
        atomicAdd(&g_cnt[dst[e]], 1);
    }
}

// per-block exclusive scan over 1024 counts; block totals -> g_bsum
__global__ void scan1_kernel() {
    __shared__ int sh[256];
    const int t = threadIdx.x;
    const int base = blockIdx.x * 1024 + t * 4;
    int c0 = 0, c1 = 0, c2 = 0, c3 = 0;
    if (base + 3 < NN) {
        int4 v = *reinterpret_cast<const int4*>(&g_cnt[base]);
        c0 = v.x; c1 = v.y; c2 = v.z; c3 = v.w;
    } else {
        if (base     < NN) c0 = g_cnt[base];
        if (base + 1 < NN) c1 = g_cnt[base + 1];
        if (base + 2 < NN) c2 = g_cnt[base + 2];
        if (base + 3 < NN) c3 = g_cnt[base + 3];
    }
    const int mysum = c0 + c1 + c2 + c3;
    sh[t] = mysum;
    __syncthreads();
    for (int off = 1; off < 256; off <<= 1) {
        int v = (t >= off) ? sh[t - off] : 0;
        __syncthreads();
        sh[t] += v;
        __syncthreads();
    }
    const int excl = sh[t] - mysum;
    if (t == 255) g_bsum[blockIdx.x] = sh[255];
    if (base     < NN) g_off[base]     = excl;
    if (base + 1 < NN) g_off[base + 1] = excl + c0;
    if (base + 2 < NN) g_off[base + 2] = excl + c0 + c1;
    if (base + 3 < NN) g_off[base + 3] = excl + c0 + c1 + c2;
}

__global__ void scan2_kernel() {   // single block: exclusive scan of block sums
    __shared__ int sh[256];
    const int t = threadIdx.x;
    int v = (t < NBLK_SCAN) ? g_bsum[t] : 0;
    sh[t] = v;
    __syncthreads();
    for (int off = 1; off < 256; off <<= 1) {
        int u = (t >= off) ? sh[t - off] : 0;
        __syncthreads();
        sh[t] += u;
        __syncthreads();
    }
    if (t < NBLK_SCAN) g_bsum[t] = sh[t] - v;
}

__global__ void scan3_kernel() {   // finalize offsets + norms
    int i = blockIdx.x * blockDim.x + threadIdx.x;
    if (i < NN) {
        g_off[i] += g_bsum[i >> 10];
        int din  = g_cnt[i];     if (din  < 1) din  = 1;
        int dout = g_deg_out[i]; if (dout < 1) dout = 1;
        g_norm_in[i]  = rsqrtf((float)din);
        g_norm_out[i] = rsqrtf((float)dout);
    }
}

__global__ void place_kernel(const int* __restrict__ src, const int* __restrict__ dst) {
    int e = blockIdx.x * blockDim.x + threadIdx.x;
    if (e < NE) {
        const int d = dst[e];
        const int pos = g_off[d] + atomicAdd(&g_fill[d], 1);
        g_csr_src[pos] = src[e];
    }
}

// ---------------- tf32 helpers ----------------
__device__ __forceinline__ void split_tf32(float v, float& hi, float& lo) {
    uint32_t hb; asm("cvt.rna.tf32.f32 %0, %1;" : "=r"(hb) : "f"(v));
    hi = __uint_as_float(hb);
    float r = v - hi;
    uint32_t lb; asm("cvt.rna.tf32.f32 %0, %1;" : "=r"(lb) : "f"(r));
    lo = __uint_as_float(lb);
}

__device__ __forceinline__ void mma_tf32(float* c, const uint32_t* a, uint32_t b0, uint32_t b1) {
    asm volatile(
        "mma.sync.aligned.m16n8k8.row.col.f32.tf32.tf32.f32 "
        "{%0,%1,%2,%3}, {%4,%5,%6,%7}, {%8,%9}, {%0,%1,%2,%3};"
        : "+f"(c[0]), "+f"(c[1]), "+f"(c[2]), "+f"(c[3])
        : "r"(a[0]), "r"(a[1]), "r"(a[2]), "r"(a[3]), "r"(b0), "r"(b1));
}

// ---------------- tensor-core GEMM (3xTF32, split accumulators): G = f(X) @ W ----------------
// SRC_H=false: A rows come from X (layer 0), scaled by norm_out.
// SRC_H=true : A rows come from g_H (device symbol, already transformed).
template <int OUTD, bool SRC_H>
__global__ void __launch_bounds__(256) mma_gemm(const float* __restrict__ X,
                                                const float* __restrict__ W) {
    constexpr int NF = OUTD / 32;
    constexpr int P  = 132;
    extern __shared__ float smem[];
    float* Wh = smem;               // [OUTD][P]
    float* Wl = Wh + OUTD * P;
    float* Ah = Wl + OUTD * P;      // [64][P]
    float* Al = Ah + 64 * P;

    const int tid  = threadIdx.x;
    const int lane = tid & 31;
    const int warp = tid >> 5;
    const int mw   = warp & 1;
    const int nw   = warp >> 1;

    for (int i = tid; i < 128 * OUTD; i += 256) {
        const int k = i / OUTD, n = i - k * OUTD;
        float hi, lo;
        split_tf32(W[i], hi, lo);
        Wh[n * P + k] = hi;
        Wl[n * P + k] = lo;
    }

    const int ntiles = (NN + 63) / 64;
    for (int tile = blockIdx.x; tile < ntiles; tile += gridDim.x) {
        __syncthreads();
        const int rowbase = tile * 64;

        for (int i = tid; i < 64 * 32; i += 256) {
            const int r = i >> 5, c4 = i & 31;
            const int row = rowbase + r;
            float4 v = make_float4(0.f, 0.f, 0.f, 0.f);
            if (row < NN) {
                if (SRC_H) {
                    v = reinterpret_cast<const float4*>(g_H + (size_t)row * 128)[c4];
                } else {
                    v = reinterpret_cast<const float4*>(X + (size_t)row * 128)[c4];
                    const float no = g_norm_out[row];
                    v.x *= no; v.y *= no; v.z *= no; v.w *= no;
                }
            }
            float4 h4, l4;
            split_tf32(v.x, h4.x, l4.x);
            split_tf32(v.y, h4.y, l4.y);
            split_tf32(v.z, h4.z, l4.z);
            split_tf32(v.w, h4.w, l4.w);
            *reinterpret_cast<float4*>(&Ah[r * P + c4 * 4]) = h4;
            *reinterpret_cast<float4*>(&Al[r * P + c4 * 4]) = l4;
        }
        __syncthreads();

        float accH[2][NF][4], accC[2][NF][4];
#pragma unroll
        for (int mf = 0; mf < 2; mf++)
#pragma unroll
            for (int nf = 0; nf < NF; nf++)
#pragma unroll
                for (int j = 0; j < 4; j++) { accH[mf][nf][j] = 0.f; accC[mf][nf][j] = 0.f; }

        const int rA = mw * 32 + (lane >> 2);
#pragma unroll 2
        for (int kk = 0; kk < 16; kk++) {
            const int k0 = kk * 8 + (lane & 3);
            uint32_t ah[2][4], al[2][4];
#pragma unroll
            for (int mf = 0; mf < 2; mf++) {
                const int r = rA + mf * 16;
                ah[mf][0] = __float_as_uint(Ah[r * P + k0]);
                ah[mf][1] = __float_as_uint(Ah[(r + 8) * P + k0]);
                ah[mf][2] = __float_as_uint(Ah[r * P + k0 + 4]);
                ah[mf][3] = __float_as_uint(Ah[(r + 8) * P + k0 + 4]);
                al[mf][0] = __float_as_uint(Al[r * P + k0]);
                al[mf][1] = __float_as_uint(Al[(r + 8) * P + k0]);
                al[mf][2] = __float_as_uint(Al[r * P + k0 + 4]);
                al[mf][3] = __float_as_uint(Al[(r + 8) * P + k0 + 4]);
            }
            uint32_t bh[NF][2], bl[NF][2];
#pragma unroll
            for (int nf = 0; nf < NF; nf++) {
                const int n = nw * (NF * 8) + nf * 8 + (lane >> 2);
                bh[nf][0] = __float_as_uint(Wh[n * P + k0]);
                bh[nf][1] = __float_as_uint(Wh[n * P + k0 + 4]);
                bl[nf][0] = __float_as_uint(Wl[n * P + k0]);
                bl[nf][1] = __float_as_uint(Wl[n * P + k0 + 4]);
            }
#pragma unroll
            for (int nf = 0; nf < NF; nf++)
#pragma unroll
                for (int mf = 0; mf < 2; mf++)
                    mma_tf32(accH[mf][nf], ah[mf], bh[nf][0], bh[nf][1]);
#pragma unroll
            for (int nf = 0; nf < NF; nf++)
#pragma unroll
                for (int mf = 0; mf < 2; mf++)
                    mma_tf32(accC[mf][nf], ah[mf], bl[nf][0], bl[nf][1]);
#pragma unroll
            for (int nf = 0; nf < NF; nf++)
#pragma unroll
                for (int mf = 0; mf < 2; mf++)
                    mma_tf32(accC[mf][nf], al[mf], bh[nf][0], bh[nf][1]);
        }

#pragma unroll
        for (int mf = 0; mf < 2; mf++) {
            const int r0 = rowbase + mw * 32 + mf * 16 + (lane >> 2);
#pragma unroll
            for (int nf = 0; nf < NF; nf++) {
                const int col = nw * (NF * 8) + nf * 8 + (lane & 3) * 2;
                if (r0 < NN)
                    *reinterpret_cast<float2*>(&g_G[(size_t)r0 * OUTD + col]) =
                        make_float2(accH[mf][nf][0] + accC[mf][nf][0],
                                    accH[mf][nf][1] + accC[mf][nf][1]);
                if (r0 + 8 < NN)
                    *reinterpret_cast<float2*>(&g_G[(size_t)(r0 + 8) * OUTD + col]) =
                        make_float2(accH[mf][nf][2] + accC[mf][nf][2],
                                    accH[mf][nf][3] + accC[mf][nf][3]);
            }
        }
    }
}

// ---------------- CSR gather aggregation + fused pointwise epilogue ----------------
// WIDTH=128: H[n] = relu(sum * ni + bias) * no   (written to g_H, feeds next GEMM)
// WIDTH=64 : out[n] = sum * ni + bias            (written to outp)
template <int WIDTH, bool FINAL>
__global__ void __launch_bounds__(256) agg_kernel(const float* __restrict__ bias,
                                                  float* __restrict__ outp) {
    const int lane = threadIdx.x & 31;
    const int gw = (blockIdx.x * blockDim.x + threadIdx.x) >> 5;
    const int nwarps = (gridDim.x * blockDim.x) >> 5;

    for (int n = gw; n < NN; n += nwarps) {
        const int beg = g_off[n];
        const int end = beg + g_cnt[n];
        if (WIDTH == 128) {
            float4 a0 = make_float4(0.f, 0.f, 0.f, 0.f);
            float4 a1 = make_float4(0.f, 0.f, 0.f, 0.f);
            int e = beg;
            for (; e + 1 < end; e += 2) {
                const int s0 = g_csr_src[e];
                const int s1 = g_csr_src[e + 1];
                const float4 v0 = reinterpret_cast<const float4*>(g_G + (size_t)s0 * 128)[lane];
                const float4 v1 = reinterpret_cast<const float4*>(g_G + (size_t)s1 * 128)[lane];
                a0.x += v0.x; a0.y += v0.y; a0.z += v0.z; a0.w += v0.w;
                a1.x += v1.x; a1.y += v1.y; a1.z += v1.z; a1.w += v1.w;
            }
            if (e < end) {
                const int s0 = g_csr_src[e];
                const float4 v0 = reinterpret_cast<const float4*>(g_G + (size_t)s0 * 128)[lane];
                a0.x += v0.x; a0.y += v0.y; a0.z += v0.z; a0.w += v0.w;
            }
            float4 s = make_float4(a0.x + a1.x, a0.y + a1.y, a0.z + a1.z, a0.w + a1.w);
            const float ni = g_norm_in[n];
            const float no = g_norm_out[n];
            const float4 bb = reinterpret_cast<const float4*>(bias)[lane];
            float4 h;
            h.x = fmaxf(fmaf(s.x, ni, bb.x), 0.f) * no;
            h.y = fmaxf(fmaf(s.y, ni, bb.y), 0.f) * no;
            h.z = fmaxf(fmaf(s.z, ni, bb.z), 0.f) * no;
            h.w = fmaxf(fmaf(s.w, ni, bb.w), 0.f) * no;
            reinterpret_cast<float4*>(g_H + (size_t)n * 128)[lane] = h;
        } else {
            float2 a0 = make_float2(0.f, 0.f);
            float2 a1 = make_float2(0.f, 0.f);
            int e = beg;
            for (; e + 1 < end; e += 2) {
                const int s0 = g_csr_src[e];
                const int s1 = g_csr_src[e + 1];
                const float2 v0 = reinterpret_cast<const float2*>(g_G + (size_t)s0 * 64)[lane];
                const float2 v1 = reinterpret_cast<const float2*>(g_G + (size_t)s1 * 64)[lane];
                a0.x += v0.x; a0.y += v0.y;
                a1.x += v1.x; a1.y += v1.y;
            }
            if (e < end) {
                const int s0 = g_csr_src[e];
                const float2 v0 = reinterpret_cast<const float2*>(g_G + (size_t)s0 * 64)[lane];
                a0.x += v0.x; a0.y += v0.y;
            }
            float2 s = make_float2(a0.x + a1.x, a0.y + a1.y);
            const float ni = g_norm_in[n];
            const float2 bb = reinterpret_cast<const float2*>(bias)[lane];
            float2 o;
            o.x = fmaf(s.x, ni, bb.x);
            o.y = fmaf(s.y, ni, bb.y);
            reinterpret_cast<float2*>(outp + (size_t)n * 64)[lane] = o;
        }
    }
}

// ---------------- launch ----------------
extern "C" void kernel_launch(void* const* d_in, const int* in_sizes, int n_in,
                              void* d_out, int out_size) {
    const float* feat = (const float*)d_in[0];
    const int*   src  = (const int*)d_in[1];
    const int*   dst  = (const int*)d_in[2];
    const float* W0   = (const float*)d_in[3];
    const float* b0   = (const float*)d_in[4];
    const float* W1   = (const float*)d_in[5];
    const float* b1   = (const float*)d_in[6];
    const float* W2   = (const float*)d_in[7];
    const float* b2   = (const float*)d_in[8];
    float* out = (float*)d_out;

    const int SM128 = (2 * 128 * 132 + 2 * 64 * 132) * 4;  // 202752 B
    const int SM64  = (2 * 64 * 132 + 2 * 64 * 132) * 4;   // 135168 B
    cudaFuncSetAttribute(mma_gemm<128, false>, cudaFuncAttributeMaxDynamicSharedMemorySize, SM128);
    cudaFuncSetAttribute(mma_gemm<128, true>,  cudaFuncAttributeMaxDynamicSharedMemorySize, SM128);
    cudaFuncSetAttribute(mma_gemm<64,  true>,  cudaFuncAttributeMaxDynamicSharedMemorySize, SM64);

    const int T = 256;
    const int GGRID = 148;
    const int AGRID = 1184;

    // CSR build + norms
    zero_kernel<<<(NN + T - 1) / T, T>>>();
    hist_kernel<<<(NE + T - 1) / T, T>>>(src, dst);
    scan1_kernel<<<NBLK_SCAN, 256>>>();
    scan2_kernel<<<1, 256>>>();
    scan3_kernel<<<(NN + T - 1) / T, T>>>();
    place_kernel<<<(NE + T - 1) / T, T>>>(src, dst);

    // layer 0: G = (feat*no) @ W0 ; H = relu(agg*ni + b0)*no
    mma_gemm<128, false><<<GGRID, T, SM128>>>(feat, W0);
    agg_kernel<128, false><<<AGRID, T>>>(b0, nullptr);

    // layer 1: G = H @ W1 ; H = relu(agg*ni + b1)*no   (A read from g_H inside kernel)
    mma_gemm<128, true><<<GGRID, T, SM128>>>(nullptr, W1);
    agg_kernel<128, false><<<AGRID, T>>>(b1, nullptr);

    // layer 2: G = H @ W2 (64-wide) ; out = agg*ni + b2
    mma_gemm<64, true><<<GGRID, T, SM64>>>(nullptr, W2);
    agg_kernel<64, true><<<AGRID, T>>>(b2, out);
}

// round 5
// speedup vs baseline: 1.7228x; 1.0631x over previous
#include <cuda_runtime.h>
#include <cuda_fp16.h>
#include <cstdint>
#include <cstddef>

#define NN 170000
#define NE 1200000
#define NBLK_SCAN 167   // ceil(NN / 1024)

// ---------------- device scratch (allocation-free) ----------------
__device__ __half g_G[(size_t)NN * 128];  // GEMM output, fp16 (gather-only consumer)
__device__ float  g_H[(size_t)NN * 128];  // post-aggregation features (fp32)
__device__ int    g_deg_out[NN];
__device__ int    g_cnt[NN];
__device__ int    g_off[NN];
__device__ int    g_fill[NN];
__device__ int    g_bsum[NBLK_SCAN];
__device__ float  g_norm_out[NN];
__device__ float  g_norm_in[NN];
__device__ int    g_csr_src[NE];

// ---------------- CSR build ----------------
__global__ void zero_kernel() {
    int i = blockIdx.x * blockDim.x + threadIdx.x;
    if (i < NN) { g_deg_out[i] = 0; g_cnt[i] = 0; g_fill[i] = 0; }
}

__global__ void hist_kernel(const int* __restrict__ src, const int* __restrict__ dst) {
    int e = blockIdx.x * blockDim.x + threadIdx.x;
    if (e < NE) {
        atomicAdd(&g_deg_out[src[e]], 1);
        atomicAdd(&g_cnt[dst[e]], 1);
    }
}

__global__ void scan1_kernel() {
    __shared__ int sh[256];
    const int t = threadIdx.x;
    const int base = blockIdx.x * 1024 + t * 4;
    int c0 = 0, c1 = 0, c2 = 0, c3 = 0;
    if (base + 3 < NN) {
        int4 v = *reinterpret_cast<const int4*>(&g_cnt[base]);
        c0 = v.x; c1 = v.y; c2 = v.z; c3 = v.w;
    } else {
        if (base     < NN) c0 = g_cnt[base];
        if (base + 1 < NN) c1 = g_cnt[base + 1];
        if (base + 2 < NN) c2 = g_cnt[base + 2];
        if (base + 3 < NN) c3 = g_cnt[base + 3];
    }
    const int mysum = c0 + c1 + c2 + c3;
    sh[t] = mysum;
    __syncthreads();
    for (int off = 1; off < 256; off <<= 1) {
        int v = (t >= off) ? sh[t - off] : 0;
        __syncthreads();
        sh[t] += v;
        __syncthreads();
    }
    const int excl = sh[t] - mysum;
    if (t == 255) g_bsum[blockIdx.x] = sh[255];
    if (base     < NN) g_off[base]     = excl;
    if (base + 1 < NN) g_off[base + 1] = excl + c0;
    if (base + 2 < NN) g_off[base + 2] = excl + c0 + c1;
    if (base + 3 < NN) g_off[base + 3] = excl + c0 + c1 + c2;
}

__global__ void scan2_kernel() {
    __shared__ int sh[256];
    const int t = threadIdx.x;
    int v = (t < NBLK_SCAN) ? g_bsum[t] : 0;
    sh[t] = v;
    __syncthreads();
    for (int off = 1; off < 256; off <<= 1) {
        int u = (t >= off) ? sh[t - off] : 0;
        __syncthreads();
        sh[t] += u;
        __syncthreads();
    }
    if (t < NBLK_SCAN) g_bsum[t] = sh[t] - v;
}

__global__ void scan3_kernel() {
    int i = blockIdx.x * blockDim.x + threadIdx.x;
    if (i < NN) {
        g_off[i] += g_bsum[i >> 10];
        int din  = g_cnt[i];     if (din  < 1) din  = 1;
        int dout = g_deg_out[i]; if (dout < 1) dout = 1;
        g_norm_in[i]  = rsqrtf((float)din);
        g_norm_out[i] = rsqrtf((float)dout);
    }
}

__global__ void place_kernel(const int* __restrict__ src, const int* __restrict__ dst) {
    int e = blockIdx.x * blockDim.x + threadIdx.x;
    if (e < NE) {
        const int d = dst[e];
        const int pos = g_off[d] + atomicAdd(&g_fill[d], 1);
        g_csr_src[pos] = src[e];
    }
}

// ---------------- tf32 helpers ----------------
__device__ __forceinline__ void split_tf32(float v, float& hi, float& lo) {
    uint32_t hb; asm("cvt.rna.tf32.f32 %0, %1;" : "=r"(hb) : "f"(v));
    hi = __uint_as_float(hb);
    float r = v - hi;
    uint32_t lb; asm("cvt.rna.tf32.f32 %0, %1;" : "=r"(lb) : "f"(r));
    lo = __uint_as_float(lb);
}

__device__ __forceinline__ void mma_tf32(float* c, const uint32_t* a, uint32_t b0, uint32_t b1) {
    asm volatile(
        "mma.sync.aligned.m16n8k8.row.col.f32.tf32.tf32.f32 "
        "{%0,%1,%2,%3}, {%4,%5,%6,%7}, {%8,%9}, {%0,%1,%2,%3};"
        : "+f"(c[0]), "+f"(c[1]), "+f"(c[2]), "+f"(c[3])
        : "r"(a[0]), "r"(a[1]), "r"(a[2]), "r"(a[3]), "r"(b0), "r"(b1));
}

// ---------------- tensor-core GEMM (3xTF32, split accumulators): G = f(X) @ W ----------------
// SRC_H=false: A rows from X (layer 0), scaled by norm_out.  SRC_H=true: A rows from g_H.
// Output stored as fp16 into g_G.
template <int OUTD, bool SRC_H>
__global__ void __launch_bounds__(256) mma_gemm(const float* __restrict__ X,
                                                const float* __restrict__ W) {
    constexpr int NF = OUTD / 32;
    constexpr int P  = 132;
    extern __shared__ float smem[];
    float* Wh = smem;
    float* Wl = Wh + OUTD * P;
    float* Ah = Wl + OUTD * P;
    float* Al = Ah + 64 * P;

    const int tid  = threadIdx.x;
    const int lane = tid & 31;
    const int warp = tid >> 5;
    const int mw   = warp & 1;
    const int nw   = warp >> 1;

    for (int i = tid; i < 128 * OUTD; i += 256) {
        const int k = i / OUTD, n = i - k * OUTD;
        float hi, lo;
        split_tf32(W[i], hi, lo);
        Wh[n * P + k] = hi;
        Wl[n * P + k] = lo;
    }

    const int ntiles = (NN + 63) / 64;
    for (int tile = blockIdx.x; tile < ntiles; tile += gridDim.x) {
        __syncthreads();
        const int rowbase = tile * 64;

        for (int i = tid; i < 64 * 32; i += 256) {
            const int r = i >> 5, c4 = i & 31;
            const int row = rowbase + r;
            float4 v = make_float4(0.f, 0.f, 0.f, 0.f);
            if (row < NN) {
                if (SRC_H) {
                    v = reinterpret_cast<const float4*>(g_H + (size_t)row * 128)[c4];
                } else {
                    v = reinterpret_cast<const float4*>(X + (size_t)row * 128)[c4];
                    const float no = g_norm_out[row];
                    v.x *= no; v.y *= no; v.z *= no; v.w *= no;
                }
            }
            float4 h4, l4;
            split_tf32(v.x, h4.x, l4.x);
            split_tf32(v.y, h4.y, l4.y);
            split_tf32(v.z, h4.z, l4.z);
            split_tf32(v.w, h4.w, l4.w);
            *reinterpret_cast<float4*>(&Ah[r * P + c4 * 4]) = h4;
            *reinterpret_cast<float4*>(&Al[r * P + c4 * 4]) = l4;
        }
        __syncthreads();

        float accH[2][NF][4], accC[2][NF][4];
#pragma unroll
        for (int mf = 0; mf < 2; mf++)
#pragma unroll
            for (int nf = 0; nf < NF; nf++)
#pragma unroll
                for (int j = 0; j < 4; j++) { accH[mf][nf][j] = 0.f; accC[mf][nf][j] = 0.f; }

        const int rA = mw * 32 + (lane >> 2);
#pragma unroll 2
        for (int kk = 0; kk < 16; kk++) {
            const int k0 = kk * 8 + (lane & 3);
            uint32_t ah[2][4], al[2][4];
#pragma unroll
            for (int mf = 0; mf < 2; mf++) {
                const int r = rA + mf * 16;
                ah[mf][0] = __float_as_uint(Ah[r * P + k0]);
                ah[mf][1] = __float_as_uint(Ah[(r + 8) * P + k0]);
                ah[mf][2] = __float_as_uint(Ah[r * P + k0 + 4]);
                ah[mf][3] = __float_as_uint(Ah[(r + 8) * P + k0 + 4]);
                al[mf][0] = __float_as_uint(Al[r * P + k0]);
                al[mf][1] = __float_as_uint(Al[(r + 8) * P + k0]);
                al[mf][2] = __float_as_uint(Al[r * P + k0 + 4]);
                al[mf][3] = __float_as_uint(Al[(r + 8) * P + k0 + 4]);
            }
            uint32_t bh[NF][2], bl[NF][2];
#pragma unroll
            for (int nf = 0; nf < NF; nf++) {
                const int n = nw * (NF * 8) + nf * 8 + (lane >> 2);
                bh[nf][0] = __float_as_uint(Wh[n * P + k0]);
                bh[nf][1] = __float_as_uint(Wh[n * P + k0 + 4]);
                bl[nf][0] = __float_as_uint(Wl[n * P + k0]);
                bl[nf][1] = __float_as_uint(Wl[n * P + k0 + 4]);
            }
#pragma unroll
            for (int nf = 0; nf < NF; nf++)
#pragma unroll
                for (int mf = 0; mf < 2; mf++)
                    mma_tf32(accH[mf][nf], ah[mf], bh[nf][0], bh[nf][1]);
#pragma unroll
            for (int nf = 0; nf < NF; nf++)
#pragma unroll
                for (int mf = 0; mf < 2; mf++)
                    mma_tf32(accC[mf][nf], ah[mf], bl[nf][0], bl[nf][1]);
#pragma unroll
            for (int nf = 0; nf < NF; nf++)
#pragma unroll
                for (int mf = 0; mf < 2; mf++)
                    mma_tf32(accC[mf][nf], al[mf], bh[nf][0], bh[nf][1]);
        }

#pragma unroll
        for (int mf = 0; mf < 2; mf++) {
            const int r0 = rowbase + mw * 32 + mf * 16 + (lane >> 2);
#pragma unroll
            for (int nf = 0; nf < NF; nf++) {
                const int col = nw * (NF * 8) + nf * 8 + (lane & 3) * 2;
                if (r0 < NN) {
                    __half2 h = __floats2half2_rn(accH[mf][nf][0] + accC[mf][nf][0],
                                                  accH[mf][nf][1] + accC[mf][nf][1]);
                    *reinterpret_cast<__half2*>(&g_G[(size_t)r0 * OUTD + col]) = h;
                }
                if (r0 + 8 < NN) {
                    __half2 h = __floats2half2_rn(accH[mf][nf][2] + accC[mf][nf][2],
                                                  accH[mf][nf][3] + accC[mf][nf][3]);
                    *reinterpret_cast<__half2*>(&g_G[(size_t)(r0 + 8) * OUTD + col]) = h;
                }
            }
        }
    }
}

// ---------------- CSR gather aggregation (fp16 rows) + fused pointwise epilogue ----------------
// WIDTH=128: H[n] = relu(sum*ni + bias)*no -> g_H (fp32)
// WIDTH=64 : out[n] = sum*ni + bias        -> outp (fp32)
template <int WIDTH, bool FINAL>
__global__ void __launch_bounds__(256) agg_kernel(const float* __restrict__ bias,
                                                  float* __restrict__ outp) {
    const int lane = threadIdx.x & 31;
    const int gw = (blockIdx.x * blockDim.x + threadIdx.x) >> 5;
    const int nwarps = (gridDim.x * blockDim.x) >> 5;

    for (int n = gw; n < NN; n += nwarps) {
        const int beg = g_off[n];
        const int end = beg + g_cnt[n];
        if (WIDTH == 128) {
            // lane covers 4 dims: one uint2 (4 halfs) per row
            float acc[4][4];  // [mlp][dim]
#pragma unroll
            for (int m = 0; m < 4; m++)
#pragma unroll
                for (int j = 0; j < 4; j++) acc[m][j] = 0.f;
            int e = beg;
            for (; e + 3 < end; e += 4) {
#pragma unroll
                for (int m = 0; m < 4; m++) {
                    const int s = g_csr_src[e + m];
                    const uint2 raw = reinterpret_cast<const uint2*>(g_G + (size_t)s * 128)[lane];
                    const float2 p0 = __half22float2(*reinterpret_cast<const __half2*>(&raw.x));
                    const float2 p1 = __half22float2(*reinterpret_cast<const __half2*>(&raw.y));
                    acc[m][0] += p0.x; acc[m][1] += p0.y; acc[m][2] += p1.x; acc[m][3] += p1.y;
                }
            }
            for (; e < end; e++) {
                const int s = g_csr_src[e];
                const uint2 raw = reinterpret_cast<const uint2*>(g_G + (size_t)s * 128)[lane];
                const float2 p0 = __half22float2(*reinterpret_cast<const __half2*>(&raw.x));
                const float2 p1 = __half22float2(*reinterpret_cast<const __half2*>(&raw.y));
                acc[0][0] += p0.x; acc[0][1] += p0.y; acc[0][2] += p1.x; acc[0][3] += p1.y;
            }
            float4 s4;
            s4.x = (acc[0][0] + acc[1][0]) + (acc[2][0] + acc[3][0]);
            s4.y = (acc[0][1] + acc[1][1]) + (acc[2][1] + acc[3][1]);
            s4.z = (acc[0][2] + acc[1][2]) + (acc[2][2] + acc[3][2]);
            s4.w = (acc[0][3] + acc[1][3]) + (acc[2][3] + acc[3][3]);
            const float ni = g_norm_in[n];
            const float no = g_norm_out[n];
            const float4 bb = reinterpret_cast<const float4*>(bias)[lane];
            float4 h;
            h.x = fmaxf(fmaf(s4.x, ni, bb.x), 0.f) * no;
            h.y = fmaxf(fmaf(s4.y, ni, bb.y), 0.f) * no;
            h.z = fmaxf(fmaf(s4.z, ni, bb.z), 0.f) * no;
            h.w = fmaxf(fmaf(s4.w, ni, bb.w), 0.f) * no;
            reinterpret_cast<float4*>(g_H + (size_t)n * 128)[lane] = h;
        } else {
            // lane covers 2 dims: one __half2 per row
            float2 acc[4];
#pragma unroll
            for (int m = 0; m < 4; m++) acc[m] = make_float2(0.f, 0.f);
            int e = beg;
            for (; e + 3 < end; e += 4) {
#pragma unroll
                for (int m = 0; m < 4; m++) {
                    const int s = g_csr_src[e + m];
                    const __half2 raw = reinterpret_cast<const __half2*>(g_G + (size_t)s * 64)[lane];
                    const float2 p = __half22float2(raw);
                    acc[m].x += p.x; acc[m].y += p.y;
                }
            }
            for (; e < end; e++) {
                const int s = g_csr_src[e];
                const __half2 raw = reinterpret_cast<const __half2*>(g_G + (size_t)s * 64)[lane];
                const float2 p = __half22float2(raw);
                acc[0].x += p.x; acc[0].y += p.y;
            }
            float2 s2 = make_float2((acc[0].x + acc[1].x) + (acc[2].x + acc[3].x),
                                    (acc[0].y + acc[1].y) + (acc[2].y + acc[3].y));
            const float ni = g_norm_in[n];
            const float2 bb = reinterpret_cast<const float2*>(bias)[lane];
            float2 o;
            o.x = fmaf(s2.x, ni, bb.x);
            o.y = fmaf(s2.y, ni, bb.y);
            reinterpret_cast<float2*>(outp + (size_t)n * 64)[lane] = o;
        }
    }
}

// ---------------- launch ----------------
extern "C" void kernel_launch(void* const* d_in, const int* in_sizes, int n_in,
                              void* d_out, int out_size) {
    const float* feat = (const float*)d_in[0];
    const int*   src  = (const int*)d_in[1];
    const int*   dst  = (const int*)d_in[2];
    const float* W0   = (const float*)d_in[3];
    const float* b0   = (const float*)d_in[4];
    const float* W1   = (const float*)d_in[5];
    const float* b1   = (const float*)d_in[6];
    const float* W2   = (const float*)d_in[7];
    const float* b2   = (const float*)d_in[8];
    float* out = (float*)d_out;

    const int SM128 = (2 * 128 * 132 + 2 * 64 * 132) * 4;  // 202752 B
    const int SM64  = (2 * 64 * 132 + 2 * 64 * 132) * 4;   // 135168 B
    cudaFuncSetAttribute(mma_gemm<128, false>, cudaFuncAttributeMaxDynamicSharedMemorySize, SM128);
    cudaFuncSetAttribute(mma_gemm<128, true>,  cudaFuncAttributeMaxDynamicSharedMemorySize, SM128);
    cudaFuncSetAttribute(mma_gemm<64,  true>,  cudaFuncAttributeMaxDynamicSharedMemorySize, SM64);

    const int T = 256;
    const int GGRID = 148;
    const int AGRID = 1184;

    // CSR build + norms
    zero_kernel<<<(NN + T - 1) / T, T>>>();
    hist_kernel<<<(NE + T - 1) / T, T>>>(src, dst);
    scan1_kernel<<<NBLK_SCAN, 256>>>();
    scan2_kernel<<<1, 256>>>();
    scan3_kernel<<<(NN + T - 1) / T, T>>>();
    place_kernel<<<(NE + T - 1) / T, T>>>(src, dst);

    // layer 0
    mma_gemm<128, false><<<GGRID, T, SM128>>>(feat, W0);
    agg_kernel<128, false><<<AGRID, T>>>(b0, nullptr);

    // layer 1
    mma_gemm<128, true><<<GGRID, T, SM128>>>(nullptr, W1);
    agg_kernel<128, false><<<AGRID, T>>>(b1, nullptr);

    // layer 2 (64-wide)
    mma_gemm<64, true><<<GGRID, T, SM64>>>(nullptr, W2);
    agg_kernel<64, true><<<AGRID, T>>>(b2, out);
}

// round 6
// speedup vs baseline: 2.4038x; 1.3953x over previous
#include <cuda_runtime.h>
#include <cuda_fp16.h>
#include <cuda_bf16.h>
#include <cstdint>
#include <cstddef>

#define NN 170000
#define NE 1200000
#define NBLK_SCAN 167   // ceil(NN / 1024)

// ---------------- device scratch (allocation-free) ----------------
__device__ __half g_G[(size_t)NN * 128];  // GEMM output, fp16 (gather-only consumer)
__device__ float  g_H[(size_t)NN * 128];  // post-aggregation features (fp32)
__device__ int    g_deg_out[NN];
__device__ int    g_cnt[NN];
__device__ int    g_off[NN];
__device__ int    g_fill[NN];
__device__ int    g_bsum[NBLK_SCAN];
__device__ float  g_norm_out[NN];
__device__ float  g_norm_in[NN];
__device__ int    g_csr_src[NE];

// ---------------- CSR build ----------------
__global__ void zero_kernel() {
    int i = blockIdx.x * blockDim.x + threadIdx.x;
    if (i < NN) { g_deg_out[i] = 0; g_cnt[i] = 0; g_fill[i] = 0; }
}

__global__ void hist_kernel(const int* __restrict__ src, const int* __restrict__ dst) {
    int e = blockIdx.x * blockDim.x + threadIdx.x;
    if (e < NE) {
        atomicAdd(&g_deg_out[src[e]], 1);
        atomicAdd(&g_cnt[dst[e]], 1);
    }
}

__global__ void scan1_kernel() {
    __shared__ int sh[256];
    const int t = threadIdx.x;
    const int base = blockIdx.x * 1024 + t * 4;
    int c0 = 0, c1 = 0, c2 = 0, c3 = 0;
    if (base + 3 < NN) {
        int4 v = *reinterpret_cast<const int4*>(&g_cnt[base]);
        c0 = v.x; c1 = v.y; c2 = v.z; c3 = v.w;
    } else {
        if (base     < NN) c0 = g_cnt[base];
        if (base + 1 < NN) c1 = g_cnt[base + 1];
        if (base + 2 < NN) c2 = g_cnt[base + 2];
        if (base + 3 < NN) c3 = g_cnt[base + 3];
    }
    const int mysum = c0 + c1 + c2 + c3;
    sh[t] = mysum;
    __syncthreads();
    for (int off = 1; off < 256; off <<= 1) {
        int v = (t >= off) ? sh[t - off] : 0;
        __syncthreads();
        sh[t] += v;
        __syncthreads();
    }
    const int excl = sh[t] - mysum;
    if (t == 255) g_bsum[blockIdx.x] = sh[255];
    if (base     < NN) g_off[base]     = excl;
    if (base + 1 < NN) g_off[base + 1] = excl + c0;
    if (base + 2 < NN) g_off[base + 2] = excl + c0 + c1;
    if (base + 3 < NN) g_off[base + 3] = excl + c0 + c1 + c2;
}

__global__ void scan2_kernel() {
    __shared__ int sh[256];
    const int t = threadIdx.x;
    int v = (t < NBLK_SCAN) ? g_bsum[t] : 0;
    sh[t] = v;
    __syncthreads();
    for (int off = 1; off < 256; off <<= 1) {
        int u = (t >= off) ? sh[t - off] : 0;
        __syncthreads();
        sh[t] += u;
        __syncthreads();
    }
    if (t < NBLK_SCAN) g_bsum[t] = sh[t] - v;
}

__global__ void scan3_kernel() {
    int i = blockIdx.x * blockDim.x + threadIdx.x;
    if (i < NN) {
        g_off[i] += g_bsum[i >> 10];
        int din  = g_cnt[i];     if (din  < 1) din  = 1;
        int dout = g_deg_out[i]; if (dout < 1) dout = 1;
        g_norm_in[i]  = rsqrtf((float)din);
        g_norm_out[i] = rsqrtf((float)dout);
    }
}

__global__ void place_kernel(const int* __restrict__ src, const int* __restrict__ dst) {
    int e = blockIdx.x * blockDim.x + threadIdx.x;
    if (e < NE) {
        const int d = dst[e];
        const int pos = g_off[d] + atomicAdd(&g_fill[d], 1);
        g_csr_src[pos] = src[e];
    }
}

// ---------------- bf16 helpers ----------------
__device__ __forceinline__ uint32_t pack_bf16_hi(float x, float y) {
    __nv_bfloat162 h = __floats2bfloat162_rn(x, y);
    return *reinterpret_cast<uint32_t*>(&h);
}

__device__ __forceinline__ void split2_bf16(float x, float y, uint32_t& hi, uint32_t& lo) {
    __nv_bfloat16 hx = __float2bfloat16_rn(x);
    __nv_bfloat16 hy = __float2bfloat16_rn(y);
    float rx = x - __bfloat162float(hx);
    float ry = y - __bfloat162float(hy);
    __nv_bfloat162 h2; h2.x = hx; h2.y = hy;
    __nv_bfloat162 l2 = __floats2bfloat162_rn(rx, ry);
    hi = *reinterpret_cast<uint32_t*>(&h2);
    lo = *reinterpret_cast<uint32_t*>(&l2);
}

__device__ __forceinline__ void mma_bf16(float* c, const uint32_t* a, uint32_t b0, uint32_t b1) {
    asm volatile(
        "mma.sync.aligned.m16n8k16.row.col.f32.bf16.bf16.f32 "
        "{%0,%1,%2,%3}, {%4,%5,%6,%7}, {%8,%9}, {%0,%1,%2,%3};"
        : "+f"(c[0]), "+f"(c[1]), "+f"(c[2]), "+f"(c[3])
        : "r"(a[0]), "r"(a[1]), "r"(a[2]), "r"(a[3]), "r"(b0), "r"(b1));
}

// ---------------- tensor-core GEMM (3x split-BF16, m16n8k16): G = f(X) @ W ----------------
// SRC_H=false: A rows from X (layer 0), scaled by norm_out.  SRC_H=true: A rows from g_H.
// Smem layout in 32-bit words (each word = 2 bf16 along k). Row stride P=68 words
// (68 mod 32 == 4 => fragment loads conflict-free: bank = (4*row + tg) mod 32 unique).
template <int OUTD, bool SRC_H>
__global__ void __launch_bounds__(256, 2) mma_gemm(const float* __restrict__ X,
                                                   const float* __restrict__ W) {
    constexpr int NF = OUTD / 32;   // n-frags per warp (4 or 2)
    constexpr int P  = 68;          // words per row
    extern __shared__ uint32_t smw[];
    uint32_t* Wh = smw;                    // [OUTD][P]
    uint32_t* Wl = Wh + OUTD * P;
    uint32_t* Ah = Wl + OUTD * P;          // [64][P]
    uint32_t* Al = Ah + 64 * P;

    const int tid  = threadIdx.x;
    const int lane = tid & 31;
    const int warp = tid >> 5;
    const int mw   = warp & 1;
    const int nw   = warp >> 1;
    const int g    = lane >> 2;     // 0..7
    const int tg   = lane & 3;      // 0..3

    // Load + split W, transposed [n][k], packed as bf16 pairs.
    // i indexes k-pairs: kp in [0,64), n in [0,OUTD)
    for (int i = tid; i < 64 * OUTD; i += 256) {
        const int kp = i / OUTD, n = i - kp * OUTD;
        const float w0 = W[(size_t)(kp * 2)     * OUTD + n];
        const float w1 = W[(size_t)(kp * 2 + 1) * OUTD + n];
        uint32_t hi, lo;
        split2_bf16(w0, w1, hi, lo);
        Wh[n * P + kp] = hi;
        Wl[n * P + kp] = lo;
    }

    const int ntiles = (NN + 63) / 64;
    for (int tile = blockIdx.x; tile < ntiles; tile += gridDim.x) {
        __syncthreads();
        const int rowbase = tile * 64;

        // Build A tile: 64 rows x 128 k, split + packed
        for (int i = tid; i < 64 * 32; i += 256) {
            const int r = i >> 5, c4 = i & 31;   // c4: float4 index (4 floats = 2 words)
            const int row = rowbase + r;
            float4 v = make_float4(0.f, 0.f, 0.f, 0.f);
            if (row < NN) {
                if (SRC_H) {
                    v = reinterpret_cast<const float4*>(g_H + (size_t)row * 128)[c4];
                } else {
                    v = reinterpret_cast<const float4*>(X + (size_t)row * 128)[c4];
                    const float no = g_norm_out[row];
                    v.x *= no; v.y *= no; v.z *= no; v.w *= no;
                }
            }
            uint32_t h0, l0, h1, l1;
            split2_bf16(v.x, v.y, h0, l0);
            split2_bf16(v.z, v.w, h1, l1);
            Ah[r * P + c4 * 2]     = h0;
            Ah[r * P + c4 * 2 + 1] = h1;
            Al[r * P + c4 * 2]     = l0;
            Al[r * P + c4 * 2 + 1] = l1;
        }
        __syncthreads();

        float accH[2][NF][4], accC[2][NF][4];
#pragma unroll
        for (int mf = 0; mf < 2; mf++)
#pragma unroll
            for (int nf = 0; nf < NF; nf++)
#pragma unroll
                for (int j = 0; j < 4; j++) { accH[mf][nf][j] = 0.f; accC[mf][nf][j] = 0.f; }

#pragma unroll
        for (int ks = 0; ks < 8; ks++) {
            const int kw = ks * 8 + tg;   // word index; +4 for second k-group
            uint32_t ah[2][4], al[2][4];
#pragma unroll
            for (int mf = 0; mf < 2; mf++) {
                const int r = mw * 32 + mf * 16 + g;
                ah[mf][0] = Ah[r * P + kw];
                ah[mf][1] = Ah[(r + 8) * P + kw];
                ah[mf][2] = Ah[r * P + kw + 4];
                ah[mf][3] = Ah[(r + 8) * P + kw + 4];
                al[mf][0] = Al[r * P + kw];
                al[mf][1] = Al[(r + 8) * P + kw];
                al[mf][2] = Al[r * P + kw + 4];
                al[mf][3] = Al[(r + 8) * P + kw + 4];
            }
            uint32_t bh[NF][2], bl[NF][2];
#pragma unroll
            for (int nf = 0; nf < NF; nf++) {
                const int n = nw * (NF * 8) + nf * 8 + g;
                bh[nf][0] = Wh[n * P + kw];
                bh[nf][1] = Wh[n * P + kw + 4];
                bl[nf][0] = Wl[n * P + kw];
                bl[nf][1] = Wl[n * P + kw + 4];
            }
#pragma unroll
            for (int nf = 0; nf < NF; nf++)
#pragma unroll
                for (int mf = 0; mf < 2; mf++)
                    mma_bf16(accH[mf][nf], ah[mf], bh[nf][0], bh[nf][1]);
#pragma unroll
            for (int nf = 0; nf < NF; nf++)
#pragma unroll
                for (int mf = 0; mf < 2; mf++)
                    mma_bf16(accC[mf][nf], ah[mf], bl[nf][0], bl[nf][1]);
#pragma unroll
            for (int nf = 0; nf < NF; nf++)
#pragma unroll
                for (int mf = 0; mf < 2; mf++)
                    mma_bf16(accC[mf][nf], al[mf], bh[nf][0], bh[nf][1]);
        }

#pragma unroll
        for (int mf = 0; mf < 2; mf++) {
            const int r0 = rowbase + mw * 32 + mf * 16 + g;
#pragma unroll
            for (int nf = 0; nf < NF; nf++) {
                const int col = nw * (NF * 8) + nf * 8 + tg * 2;
                if (r0 < NN) {
                    __half2 h = __floats2half2_rn(accH[mf][nf][0] + accC[mf][nf][0],
                                                  accH[mf][nf][1] + accC[mf][nf][1]);
                    *reinterpret_cast<__half2*>(&g_G[(size_t)r0 * OUTD + col]) = h;
                }
                if (r0 + 8 < NN) {
                    __half2 h = __floats2half2_rn(accH[mf][nf][2] + accC[mf][nf][2],
                                                  accH[mf][nf][3] + accC[mf][nf][3]);
                    *reinterpret_cast<__half2*>(&g_G[(size_t)(r0 + 8) * OUTD + col]) = h;
                }
            }
        }
    }
}

// ---------------- CSR gather aggregation (fp16 rows) + fused pointwise epilogue ----------------
template <int WIDTH, bool FINAL>
__global__ void __launch_bounds__(256) agg_kernel(const float* __restrict__ bias,
                                                  float* __restrict__ outp) {
    const int lane = threadIdx.x & 31;
    const int gw = (blockIdx.x * blockDim.x + threadIdx.x) >> 5;
    const int nwarps = (gridDim.x * blockDim.x) >> 5;

    for (int n = gw; n < NN; n += nwarps) {
        const int beg = g_off[n];
        const int end = beg + g_cnt[n];
        if (WIDTH == 128) {
            float acc[4][4];
#pragma unroll
            for (int m = 0; m < 4; m++)
#pragma unroll
                for (int j = 0; j < 4; j++) acc[m][j] = 0.f;
            int e = beg;
            for (; e + 3 < end; e += 4) {
#pragma unroll
                for (int m = 0; m < 4; m++) {
                    const int s = g_csr_src[e + m];
                    const uint2 raw = reinterpret_cast<const uint2*>(g_G + (size_t)s * 128)[lane];
                    const float2 p0 = __half22float2(*reinterpret_cast<const __half2*>(&raw.x));
                    const float2 p1 = __half22float2(*reinterpret_cast<const __half2*>(&raw.y));
                    acc[m][0] += p0.x; acc[m][1] += p0.y; acc[m][2] += p1.x; acc[m][3] += p1.y;
                }
            }
            for (; e < end; e++) {
                const int s = g_csr_src[e];
                const uint2 raw = reinterpret_cast<const uint2*>(g_G + (size_t)s * 128)[lane];
                const float2 p0 = __half22float2(*reinterpret_cast<const __half2*>(&raw.x));
                const float2 p1 = __half22float2(*reinterpret_cast<const __half2*>(&raw.y));
                acc[0][0] += p0.x; acc[0][1] += p0.y; acc[0][2] += p1.x; acc[0][3] += p1.y;
            }
            float4 s4;
            s4.x = (acc[0][0] + acc[1][0]) + (acc[2][0] + acc[3][0]);
            s4.y = (acc[0][1] + acc[1][1]) + (acc[2][1] + acc[3][1]);
            s4.z = (acc[0][2] + acc[1][2]) + (acc[2][2] + acc[3][2]);
            s4.w = (acc[0][3] + acc[1][3]) + (acc[2][3] + acc[3][3]);
            const float ni = g_norm_in[n];
            const float no = g_norm_out[n];
            const float4 bb = reinterpret_cast<const float4*>(bias)[lane];
            float4 h;
            h.x = fmaxf(fmaf(s4.x, ni, bb.x), 0.f) * no;
            h.y = fmaxf(fmaf(s4.y, ni, bb.y), 0.f) * no;
            h.z = fmaxf(fmaf(s4.z, ni, bb.z), 0.f) * no;
            h.w = fmaxf(fmaf(s4.w, ni, bb.w), 0.f) * no;
            reinterpret_cast<float4*>(g_H + (size_t)n * 128)[lane] = h;
        } else {
            float2 acc[4];
#pragma unroll
            for (int m = 0; m < 4; m++) acc[m] = make_float2(0.f, 0.f);
            int e = beg;
            for (; e + 3 < end; e += 4) {
#pragma unroll
                for (int m = 0; m < 4; m++) {
                    const int s = g_csr_src[e + m];
                    const __half2 raw = reinterpret_cast<const __half2*>(g_G + (size_t)s * 64)[lane];
                    const float2 p = __half22float2(raw);
                    acc[m].x += p.x; acc[m].y += p.y;
                }
            }
            for (; e < end; e++) {
                const int s = g_csr_src[e];
                const __half2 raw = reinterpret_cast<const __half2*>(g_G + (size_t)s * 64)[lane];
                const float2 p = __half22float2(raw);
                acc[0].x += p.x; acc[0].y += p.y;
            }
            float2 s2 = make_float2((acc[0].x + acc[1].x) + (acc[2].x + acc[3].x),
                                    (acc[0].y + acc[1].y) + (acc[2].y + acc[3].y));
            const float ni = g_norm_in[n];
            const float2 bb = reinterpret_cast<const float2*>(bias)[lane];
            float2 o;
            o.x = fmaf(s2.x, ni, bb.x);
            o.y = fmaf(s2.y, ni, bb.y);
            reinterpret_cast<float2*>(outp + (size_t)n * 64)[lane] = o;
        }
    }
}

// ---------------- launch ----------------
extern "C" void kernel_launch(void* const* d_in, const int* in_sizes, int n_in,
                              void* d_out, int out_size) {
    const float* feat = (const float*)d_in[0];
    const int*   src  = (const int*)d_in[1];
    const int*   dst  = (const int*)d_in[2];
    const float* W0   = (const float*)d_in[3];
    const float* b0   = (const float*)d_in[4];
    const float* W1   = (const float*)d_in[5];
    const float* b1   = (const float*)d_in[6];
    const float* W2   = (const float*)d_in[7];
    const float* b2   = (const float*)d_in[8];
    float* out = (float*)d_out;

    const int SM128 = (2 * 128 * 68 + 2 * 64 * 68) * 4;  // 104448 B
    const int SM64  = (2 * 64 * 68 + 2 * 64 * 68) * 4;   // 69632 B
    cudaFuncSetAttribute(mma_gemm<128, false>, cudaFuncAttributeMaxDynamicSharedMemorySize, SM128);
    cudaFuncSetAttribute(mma_gemm<128, true>,  cudaFuncAttributeMaxDynamicSharedMemorySize, SM128);
    cudaFuncSetAttribute(mma_gemm<64,  true>,  cudaFuncAttributeMaxDynamicSharedMemorySize, SM64);

    const int T = 256;
    const int GGRID = 296;   // 2 CTAs/SM
    const int AGRID = 1184;

    // CSR build + norms
    zero_kernel<<<(NN + T - 1) / T, T>>>();
    hist_kernel<<<(NE + T - 1) / T, T>>>(src, dst);
    scan1_kernel<<<NBLK_SCAN, 256>>>();
    scan2_kernel<<<1, 256>>>();
    scan3_kernel<<<(NN + T - 1) / T, T>>>();
    place_kernel<<<(NE + T - 1) / T, T>>>(src, dst);

    // layer 0
    mma_gemm<128, false><<<GGRID, T, SM128>>>(feat, W0);
    agg_kernel<128, false><<<AGRID, T>>>(b0, nullptr);

    // layer 1
    mma_gemm<128, true><<<GGRID, T, SM128>>>(nullptr, W1);
    agg_kernel<128, false><<<AGRID, T>>>(b1, nullptr);

    // layer 2 (64-wide)
    mma_gemm<64, true><<<GGRID, T, SM64>>>(nullptr, W2);
    agg_kernel<64, true><<<AGRID, T>>>(b2, out);
}

// round 7
// speedup vs baseline: 2.5494x; 1.0606x over previous
#include <cuda_runtime.h>
#include <cuda_fp16.h>
#include <cuda_bf16.h>
#include <cstdint>
#include <cstddef>

#define NN 170000
#define NE 1200000
#define NBLK_SCAN 167   // ceil(NN / 1024)

// ---------------- device scratch (allocation-free) ----------------
__device__ __half g_G[(size_t)NN * 128];  // GEMM output, fp16 (gather-only consumer)
__device__ float  g_H[(size_t)NN * 128];  // post-aggregation features (fp32)
__device__ int    g_deg_out[NN];
__device__ int    g_cnt[NN];
__device__ int    g_off[NN];
__device__ int    g_fill[NN];
__device__ int    g_bsum[NBLK_SCAN];
__device__ float  g_norm_out[NN];
__device__ float  g_norm_in[NN];
__device__ int    g_csr_src[NE];

// ---------------- CSR build ----------------
__global__ void zero_kernel() {
    int i = blockIdx.x * blockDim.x + threadIdx.x;
    if (i < NN) { g_deg_out[i] = 0; g_cnt[i] = 0; g_fill[i] = 0; }
}

__global__ void hist_kernel(const int* __restrict__ src, const int* __restrict__ dst) {
    int e = blockIdx.x * blockDim.x + threadIdx.x;
    if (e < NE) {
        atomicAdd(&g_deg_out[src[e]], 1);
        atomicAdd(&g_cnt[dst[e]], 1);
    }
}

__global__ void scan1_kernel() {
    __shared__ int sh[256];
    const int t = threadIdx.x;
    const int base = blockIdx.x * 1024 + t * 4;
    int c0 = 0, c1 = 0, c2 = 0, c3 = 0;
    if (base + 3 < NN) {
        int4 v = *reinterpret_cast<const int4*>(&g_cnt[base]);
        c0 = v.x; c1 = v.y; c2 = v.z; c3 = v.w;
    } else {
        if (base     < NN) c0 = g_cnt[base];
        if (base + 1 < NN) c1 = g_cnt[base + 1];
        if (base + 2 < NN) c2 = g_cnt[base + 2];
        if (base + 3 < NN) c3 = g_cnt[base + 3];
    }
    const int mysum = c0 + c1 + c2 + c3;
    sh[t] = mysum;
    __syncthreads();
    for (int off = 1; off < 256; off <<= 1) {
        int v = (t >= off) ? sh[t - off] : 0;
        __syncthreads();
        sh[t] += v;
        __syncthreads();
    }
    const int excl = sh[t] - mysum;
    if (t == 255) g_bsum[blockIdx.x] = sh[255];
    if (base     < NN) g_off[base]     = excl;
    if (base + 1 < NN) g_off[base + 1] = excl + c0;
    if (base + 2 < NN) g_off[base + 2] = excl + c0 + c1;
    if (base + 3 < NN) g_off[base + 3] = excl + c0 + c1 + c2;
}

__global__ void scan2_kernel() {
    __shared__ int sh[256];
    const int t = threadIdx.x;
    int v = (t < NBLK_SCAN) ? g_bsum[t] : 0;
    sh[t] = v;
    __syncthreads();
    for (int off = 1; off < 256; off <<= 1) {
        int u = (t >= off) ? sh[t - off] : 0;
        __syncthreads();
        sh[t] += u;
        __syncthreads();
    }
    if (t < NBLK_SCAN) g_bsum[t] = sh[t] - v;
}

__global__ void scan3_kernel() {
    int i = blockIdx.x * blockDim.x + threadIdx.x;
    if (i < NN) {
        g_off[i] += g_bsum[i >> 10];
        int din  = g_cnt[i];     if (din  < 1) din  = 1;
        int dout = g_deg_out[i]; if (dout < 1) dout = 1;
        g_norm_in[i]  = rsqrtf((float)din);
        g_norm_out[i] = rsqrtf((float)dout);
    }
}

__global__ void place_kernel(const int* __restrict__ src, const int* __restrict__ dst) {
    int e = blockIdx.x * blockDim.x + threadIdx.x;
    if (e < NE) {
        const int d = dst[e];
        const int pos = g_off[d] + atomicAdd(&g_fill[d], 1);
        g_csr_src[pos] = src[e];
    }
}

// ---------------- bf16 helpers ----------------
__device__ __forceinline__ void split2_bf16(float x, float y, uint32_t& hi, uint32_t& lo) {
    __nv_bfloat16 hx = __float2bfloat16_rn(x);
    __nv_bfloat16 hy = __float2bfloat16_rn(y);
    float rx = x - __bfloat162float(hx);
    float ry = y - __bfloat162float(hy);
    __nv_bfloat162 h2; h2.x = hx; h2.y = hy;
    __nv_bfloat162 l2 = __floats2bfloat162_rn(rx, ry);
    hi = *reinterpret_cast<uint32_t*>(&h2);
    lo = *reinterpret_cast<uint32_t*>(&l2);
}

__device__ __forceinline__ void mma_bf16(float* c, const uint32_t* a, uint32_t b0, uint32_t b1) {
    asm volatile(
        "mma.sync.aligned.m16n8k16.row.col.f32.bf16.bf16.f32 "
        "{%0,%1,%2,%3}, {%4,%5,%6,%7}, {%8,%9}, {%0,%1,%2,%3};"
        : "+f"(c[0]), "+f"(c[1]), "+f"(c[2]), "+f"(c[3])
        : "r"(a[0]), "r"(a[1]), "r"(a[2]), "r"(a[3]), "r"(b0), "r"(b1));
}

// ---------------- tensor-core GEMM (3x split-BF16, m16n8k16): G = f(X) @ W ----------------
template <int OUTD, bool SRC_H>
__global__ void __launch_bounds__(256, 2) mma_gemm(const float* __restrict__ X,
                                                   const float* __restrict__ W) {
    constexpr int NF = OUTD / 32;
    constexpr int P  = 68;          // words per row; 68 mod 32 == 4 => conflict-free frags
    extern __shared__ uint32_t smw[];
    uint32_t* Wh = smw;                    // [OUTD][P]
    uint32_t* Wl = Wh + OUTD * P;
    uint32_t* Ah = Wl + OUTD * P;          // [64][P]
    uint32_t* Al = Ah + 64 * P;

    const int tid  = threadIdx.x;
    const int lane = tid & 31;
    const int warp = tid >> 5;
    const int mw   = warp & 1;
    const int nw   = warp >> 1;
    const int g    = lane >> 2;
    const int tg   = lane & 3;

    for (int i = tid; i < 64 * OUTD; i += 256) {
        const int kp = i / OUTD, n = i - kp * OUTD;
        const float w0 = W[(size_t)(kp * 2)     * OUTD + n];
        const float w1 = W[(size_t)(kp * 2 + 1) * OUTD + n];
        uint32_t hi, lo;
        split2_bf16(w0, w1, hi, lo);
        Wh[n * P + kp] = hi;
        Wl[n * P + kp] = lo;
    }

    const int ntiles = (NN + 63) / 64;
    for (int tile = blockIdx.x; tile < ntiles; tile += gridDim.x) {
        __syncthreads();
        const int rowbase = tile * 64;

        for (int i = tid; i < 64 * 32; i += 256) {
            const int r = i >> 5, c4 = i & 31;
            const int row = rowbase + r;
            float4 v = make_float4(0.f, 0.f, 0.f, 0.f);
            if (row < NN) {
                if (SRC_H) {
                    v = reinterpret_cast<const float4*>(g_H + (size_t)row * 128)[c4];
                } else {
                    v = reinterpret_cast<const float4*>(X + (size_t)row * 128)[c4];
                    const float no = g_norm_out[row];
                    v.x *= no; v.y *= no; v.z *= no; v.w *= no;
                }
            }
            uint32_t h0, l0, h1, l1;
            split2_bf16(v.x, v.y, h0, l0);
            split2_bf16(v.z, v.w, h1, l1);
            Ah[r * P + c4 * 2]     = h0;
            Ah[r * P + c4 * 2 + 1] = h1;
            Al[r * P + c4 * 2]     = l0;
            Al[r * P + c4 * 2 + 1] = l1;
        }
        __syncthreads();

        float accH[2][NF][4], accC[2][NF][4];
#pragma unroll
        for (int mf = 0; mf < 2; mf++)
#pragma unroll
            for (int nf = 0; nf < NF; nf++)
#pragma unroll
                for (int j = 0; j < 4; j++) { accH[mf][nf][j] = 0.f; accC[mf][nf][j] = 0.f; }

#pragma unroll
        for (int ks = 0; ks < 8; ks++) {
            const int kw = ks * 8 + tg;
            uint32_t ah[2][4], al[2][4];
#pragma unroll
            for (int mf = 0; mf < 2; mf++) {
                const int r = mw * 32 + mf * 16 + g;
                ah[mf][0] = Ah[r * P + kw];
                ah[mf][1] = Ah[(r + 8) * P + kw];
                ah[mf][2] = Ah[r * P + kw + 4];
                ah[mf][3] = Ah[(r + 8) * P + kw + 4];
                al[mf][0] = Al[r * P + kw];
                al[mf][1] = Al[(r + 8) * P + kw];
                al[mf][2] = Al[r * P + kw + 4];
                al[mf][3] = Al[(r + 8) * P + kw + 4];
            }
            uint32_t bh[NF][2], bl[NF][2];
#pragma unroll
            for (int nf = 0; nf < NF; nf++) {
                const int n = nw * (NF * 8) + nf * 8 + g;
                bh[nf][0] = Wh[n * P + kw];
                bh[nf][1] = Wh[n * P + kw + 4];
                bl[nf][0] = Wl[n * P + kw];
                bl[nf][1] = Wl[n * P + kw + 4];
            }
#pragma unroll
            for (int nf = 0; nf < NF; nf++)
#pragma unroll
                for (int mf = 0; mf < 2; mf++)
                    mma_bf16(accH[mf][nf], ah[mf], bh[nf][0], bh[nf][1]);
#pragma unroll
            for (int nf = 0; nf < NF; nf++)
#pragma unroll
                for (int mf = 0; mf < 2; mf++)
                    mma_bf16(accC[mf][nf], ah[mf], bl[nf][0], bl[nf][1]);
#pragma unroll
            for (int nf = 0; nf < NF; nf++)
#pragma unroll
                for (int mf = 0; mf < 2; mf++)
                    mma_bf16(accC[mf][nf], al[mf], bh[nf][0], bh[nf][1]);
        }

#pragma unroll
        for (int mf = 0; mf < 2; mf++) {
            const int r0 = rowbase + mw * 32 + mf * 16 + g;
#pragma unroll
            for (int nf = 0; nf < NF; nf++) {
                const int col = nw * (NF * 8) + nf * 8 + tg * 2;
                if (r0 < NN) {
                    __half2 h = __floats2half2_rn(accH[mf][nf][0] + accC[mf][nf][0],
                                                  accH[mf][nf][1] + accC[mf][nf][1]);
                    *reinterpret_cast<__half2*>(&g_G[(size_t)r0 * OUTD + col]) = h;
                }
                if (r0 + 8 < NN) {
                    __half2 h = __floats2half2_rn(accH[mf][nf][2] + accC[mf][nf][2],
                                                  accH[mf][nf][3] + accC[mf][nf][3]);
                    *reinterpret_cast<__half2*>(&g_G[(size_t)(r0 + 8) * OUTD + col]) = h;
                }
            }
        }
    }
}

// ---------------- CSR gather aggregation: predicated batch-8 ----------------
// Always 8 independent row loads in flight per chunk; invalid slots clamp the index
// and zero-select the loaded bits (zeros are additive identity; no NaN hazard).
template <int WIDTH, bool FINAL>
__global__ void __launch_bounds__(256) agg_kernel(const float* __restrict__ bias,
                                                  float* __restrict__ outp) {
    const int lane = threadIdx.x & 31;
    const int gw = (blockIdx.x * blockDim.x + threadIdx.x) >> 5;
    const int nwarps = (gridDim.x * blockDim.x) >> 5;

    for (int n = gw; n < NN; n += nwarps) {
        const int beg = g_off[n];
        const int deg = g_cnt[n];
        const int end = beg + deg;

        if (WIDTH == 128) {
            float accA[4] = {0.f, 0.f, 0.f, 0.f};
            float accB[4] = {0.f, 0.f, 0.f, 0.f};
            if (deg > 0) {
                for (int base = beg; base < end; base += 8) {
                    uint2 raw[8];
#pragma unroll
                    for (int m = 0; m < 8; m++) {
                        const int ee = base + m;
                        const bool valid = ee < end;
                        const int s = __ldg(&g_csr_src[valid ? ee : beg]);
                        uint2 r = reinterpret_cast<const uint2*>(g_G + (size_t)s * 128)[lane];
                        raw[m].x = valid ? r.x : 0u;
                        raw[m].y = valid ? r.y : 0u;
                    }
#pragma unroll
                    for (int m = 0; m < 8; m++) {
                        const float2 p0 = __half22float2(*reinterpret_cast<const __half2*>(&raw[m].x));
                        const float2 p1 = __half22float2(*reinterpret_cast<const __half2*>(&raw[m].y));
                        float* acc = (m & 1) ? accB : accA;
                        acc[0] += p0.x; acc[1] += p0.y; acc[2] += p1.x; acc[3] += p1.y;
                    }
                }
            }
            const float ni = g_norm_in[n];
            const float no = g_norm_out[n];
            const float4 bb = reinterpret_cast<const float4*>(bias)[lane];
            float4 h;
            h.x = fmaxf(fmaf(accA[0] + accB[0], ni, bb.x), 0.f) * no;
            h.y = fmaxf(fmaf(accA[1] + accB[1], ni, bb.y), 0.f) * no;
            h.z = fmaxf(fmaf(accA[2] + accB[2], ni, bb.z), 0.f) * no;
            h.w = fmaxf(fmaf(accA[3] + accB[3], ni, bb.w), 0.f) * no;
            reinterpret_cast<float4*>(g_H + (size_t)n * 128)[lane] = h;
        } else {
            float accA[2] = {0.f, 0.f};
            float accB[2] = {0.f, 0.f};
            if (deg > 0) {
                for (int base = beg; base < end; base += 8) {
                    uint32_t raw[8];
#pragma unroll
                    for (int m = 0; m < 8; m++) {
                        const int ee = base + m;
                        const bool valid = ee < end;
                        const int s = __ldg(&g_csr_src[valid ? ee : beg]);
                        uint32_t r = reinterpret_cast<const uint32_t*>(g_G + (size_t)s * 64)[lane];
                        raw[m] = valid ? r : 0u;
                    }
#pragma unroll
                    for (int m = 0; m < 8; m++) {
                        const float2 p = __half22float2(*reinterpret_cast<const __half2*>(&raw[m]));
                        float* acc = (m & 1) ? accB : accA;
                        acc[0] += p.x; acc[1] += p.y;
                    }
                }
            }
            const float ni = g_norm_in[n];
            const float2 bb = reinterpret_cast<const float2*>(bias)[lane];
            float2 o;
            o.x = fmaf(accA[0] + accB[0], ni, bb.x);
            o.y = fmaf(accA[1] + accB[1], ni, bb.y);
            reinterpret_cast<float2*>(outp + (size_t)n * 64)[lane] = o;
        }
    }
}

// ---------------- launch ----------------
extern "C" void kernel_launch(void* const* d_in, const int* in_sizes, int n_in,
                              void* d_out, int out_size) {
    const float* feat = (const float*)d_in[0];
    const int*   src  = (const int*)d_in[1];
    const int*   dst  = (const int*)d_in[2];
    const float* W0   = (const float*)d_in[3];
    const float* b0   = (const float*)d_in[4];
    const float* W1   = (const float*)d_in[5];
    const float* b1   = (const float*)d_in[6];
    const float* W2   = (const float*)d_in[7];
    const float* b2   = (const float*)d_in[8];
    float* out = (float*)d_out;

    const int SM128 = (2 * 128 * 68 + 2 * 64 * 68) * 4;  // 104448 B
    const int SM64  = (2 * 64 * 68 + 2 * 64 * 68) * 4;   // 69632 B
    cudaFuncSetAttribute(mma_gemm<128, false>, cudaFuncAttributeMaxDynamicSharedMemorySize, SM128);
    cudaFuncSetAttribute(mma_gemm<128, true>,  cudaFuncAttributeMaxDynamicSharedMemorySize, SM128);
    cudaFuncSetAttribute(mma_gemm<64,  true>,  cudaFuncAttributeMaxDynamicSharedMemorySize, SM64);

    const int T = 256;
    const int GGRID = 296;   // 2 CTAs/SM
    const int AGRID = 1184;  // exactly resident: 8 blocks/SM

    // CSR build + norms
    zero_kernel<<<(NN + T - 1) / T, T>>>();
    hist_kernel<<<(NE + T - 1) / T, T>>>(src, dst);
    scan1_kernel<<<NBLK_SCAN, 256>>>();
    scan2_kernel<<<1, 256>>>();
    scan3_kernel<<<(NN + T - 1) / T, T>>>();
    place_kernel<<<(NE + T - 1) / T, T>>>(src, dst);

    // layer 0
    mma_gemm<128, false><<<GGRID, T, SM128>>>(feat, W0);
    agg_kernel<128, false><<<AGRID, T>>>(b0, nullptr);

    // layer 1
    mma_gemm<128, true><<<GGRID, T, SM128>>>(nullptr, W1);
    agg_kernel<128, false><<<AGRID, T>>>(b1, nullptr);

    // layer 2 (64-wide)
    mma_gemm<64, true><<<GGRID, T, SM64>>>(nullptr, W2);
    agg_kernel<64, true><<<AGRID, T>>>(b2, out);
}

// round 8
// speedup vs baseline: 3.2513x; 1.2753x over previous
#include <cuda_runtime.h>
#include <cuda_fp16.h>
#include <cstdint>
#include <cstddef>

#define NN 170000
#define NE 1200000
#define NBLK_SCAN 167   // ceil(NN / 1024)

// ---------------- device scratch (allocation-free) ----------------
__device__ __half g_G[(size_t)NN * 128];  // GEMM output (fp16)
__device__ __half g_H[(size_t)NN * 128];  // post-aggregation features (fp16)
__device__ int    g_deg_out[NN];
__device__ int    g_cnt[NN];
__device__ int    g_off[NN];
__device__ int    g_fill[NN];
__device__ int    g_bsum[NBLK_SCAN];
__device__ float  g_norm_out[NN];
__device__ float  g_norm_in[NN];
__device__ int    g_csr_src[NE];

// ---------------- CSR build ----------------
__global__ void zero_kernel() {
    int i = blockIdx.x * blockDim.x + threadIdx.x;
    if (i < NN) { g_deg_out[i] = 0; g_cnt[i] = 0; g_fill[i] = 0; }
}

__global__ void hist_kernel(const int* __restrict__ src, const int* __restrict__ dst) {
    int e = blockIdx.x * blockDim.x + threadIdx.x;
    if (e < NE) {
        atomicAdd(&g_deg_out[src[e]], 1);
        atomicAdd(&g_cnt[dst[e]], 1);
    }
}

__global__ void scan1_kernel() {
    __shared__ int sh[256];
    const int t = threadIdx.x;
    const int base = blockIdx.x * 1024 + t * 4;
    int c0 = 0, c1 = 0, c2 = 0, c3 = 0;
    if (base + 3 < NN) {
        int4 v = *reinterpret_cast<const int4*>(&g_cnt[base]);
        c0 = v.x; c1 = v.y; c2 = v.z; c3 = v.w;
    } else {
        if (base     < NN) c0 = g_cnt[base];
        if (base + 1 < NN) c1 = g_cnt[base + 1];
        if (base + 2 < NN) c2 = g_cnt[base + 2];
        if (base + 3 < NN) c3 = g_cnt[base + 3];
    }
    const int mysum = c0 + c1 + c2 + c3;
    sh[t] = mysum;
    __syncthreads();
    for (int off = 1; off < 256; off <<= 1) {
        int v = (t >= off) ? sh[t - off] : 0;
        __syncthreads();
        sh[t] += v;
        __syncthreads();
    }
    const int excl = sh[t] - mysum;
    if (t == 255) g_bsum[blockIdx.x] = sh[255];
    if (base     < NN) g_off[base]     = excl;
    if (base + 1 < NN) g_off[base + 1] = excl + c0;
    if (base + 2 < NN) g_off[base + 2] = excl + c0 + c1;
    if (base + 3 < NN) g_off[base + 3] = excl + c0 + c1 + c2;
}

__global__ void scan2_kernel() {
    __shared__ int sh[256];
    const int t = threadIdx.x;
    int v = (t < NBLK_SCAN) ? g_bsum[t] : 0;
    sh[t] = v;
    __syncthreads();
    for (int off = 1; off < 256; off <<= 1) {
        int u = (t >= off) ? sh[t - off] : 0;
        __syncthreads();
        sh[t] += u;
        __syncthreads();
    }
    if (t < NBLK_SCAN) g_bsum[t] = sh[t] - v;
}

__global__ void scan3_kernel() {
    int i = blockIdx.x * blockDim.x + threadIdx.x;
    if (i < NN) {
        g_off[i] += g_bsum[i >> 10];
        int din  = g_cnt[i];     if (din  < 1) din  = 1;
        int dout = g_deg_out[i]; if (dout < 1) dout = 1;
        g_norm_in[i]  = rsqrtf((float)din);
        g_norm_out[i] = rsqrtf((float)dout);
    }
}

__global__ void place_kernel(const int* __restrict__ src, const int* __restrict__ dst) {
    int e = blockIdx.x * blockDim.x + threadIdx.x;
    if (e < NE) {
        const int d = dst[e];
        const int pos = g_off[d] + atomicAdd(&g_fill[d], 1);
        g_csr_src[pos] = src[e];
    }
}

// ---------------- fp16 mma ----------------
__device__ __forceinline__ void mma_f16(float* c, const uint32_t* a, uint32_t b0, uint32_t b1) {
    asm volatile(
        "mma.sync.aligned.m16n8k16.row.col.f32.f16.f16.f32 "
        "{%0,%1,%2,%3}, {%4,%5,%6,%7}, {%8,%9}, {%0,%1,%2,%3};"
        : "+f"(c[0]), "+f"(c[1]), "+f"(c[2]), "+f"(c[3])
        : "r"(a[0]), "r"(a[1]), "r"(a[2]), "r"(a[3]), "r"(b0), "r"(b1));
}

// ---------------- tensor-core GEMM (single-pass fp16, m16n8k16): G = f(X) @ W ----------------
// SRC_H=false: A rows = X * norm_out (fp32 -> fp16).  SRC_H=true: A rows = g_H (fp16 bit-copy).
// Smem in 32-bit words (2 halfs along k), row stride P=68 (68%32==4 => conflict-free frags).
template <int OUTD, bool SRC_H>
__global__ void __launch_bounds__(256, 3) mma_gemm(const float* __restrict__ X,
                                                   const float* __restrict__ W) {
    constexpr int NF = OUTD / 32;
    constexpr int P  = 68;
    extern __shared__ uint32_t smw[];
    uint32_t* Wh = smw;                    // [OUTD][P]
    uint32_t* Ah = Wh + OUTD * P;          // [64][P]

    const int tid  = threadIdx.x;
    const int lane = tid & 31;
    const int warp = tid >> 5;
    const int mw   = warp & 1;
    const int nw   = warp >> 1;
    const int g    = lane >> 2;
    const int tg   = lane & 3;

    // W -> smem, transposed [n][k], fp16 pairs
    for (int i = tid; i < 64 * OUTD; i += 256) {
        const int kp = i / OUTD, n = i - kp * OUTD;
        const float w0 = W[(size_t)(kp * 2)     * OUTD + n];
        const float w1 = W[(size_t)(kp * 2 + 1) * OUTD + n];
        __half2 h = __floats2half2_rn(w0, w1);
        Wh[n * P + kp] = *reinterpret_cast<uint32_t*>(&h);
    }

    const int ntiles = (NN + 63) / 64;
    for (int tile = blockIdx.x; tile < ntiles; tile += gridDim.x) {
        __syncthreads();
        const int rowbase = tile * 64;

        // A tile: 64 rows x 64 words
        for (int i = tid; i < 64 * 32; i += 256) {
            const int r = i >> 5, c4 = i & 31;   // c4 = pair-of-words index
            const int row = rowbase + r;
            uint32_t w0 = 0, w1 = 0;
            if (row < NN) {
                if (SRC_H) {
                    const uint2 raw = reinterpret_cast<const uint2*>(g_H + (size_t)row * 128)[c4];
                    w0 = raw.x; w1 = raw.y;
                } else {
                    float4 v = reinterpret_cast<const float4*>(X + (size_t)row * 128)[c4];
                    const float no = g_norm_out[row];
                    __half2 h0 = __floats2half2_rn(v.x * no, v.y * no);
                    __half2 h1 = __floats2half2_rn(v.z * no, v.w * no);
                    w0 = *reinterpret_cast<uint32_t*>(&h0);
                    w1 = *reinterpret_cast<uint32_t*>(&h1);
                }
            }
            Ah[r * P + c4 * 2]     = w0;
            Ah[r * P + c4 * 2 + 1] = w1;
        }
        __syncthreads();

        float acc[2][NF][4];
#pragma unroll
        for (int mf = 0; mf < 2; mf++)
#pragma unroll
            for (int nf = 0; nf < NF; nf++)
#pragma unroll
                for (int j = 0; j < 4; j++) acc[mf][nf][j] = 0.f;

#pragma unroll
        for (int ks = 0; ks < 8; ks++) {
            const int kw = ks * 8 + tg;
            uint32_t ah[2][4];
#pragma unroll
            for (int mf = 0; mf < 2; mf++) {
                const int r = mw * 32 + mf * 16 + g;
                ah[mf][0] = Ah[r * P + kw];
                ah[mf][1] = Ah[(r + 8) * P + kw];
                ah[mf][2] = Ah[r * P + kw + 4];
                ah[mf][3] = Ah[(r + 8) * P + kw + 4];
            }
#pragma unroll
            for (int nf = 0; nf < NF; nf++) {
                const int n = nw * (NF * 8) + nf * 8 + g;
                const uint32_t b0 = Wh[n * P + kw];
                const uint32_t b1 = Wh[n * P + kw + 4];
#pragma unroll
                for (int mf = 0; mf < 2; mf++)
                    mma_f16(acc[mf][nf], ah[mf], b0, b1);
            }
        }

#pragma unroll
        for (int mf = 0; mf < 2; mf++) {
            const int r0 = rowbase + mw * 32 + mf * 16 + g;
#pragma unroll
            for (int nf = 0; nf < NF; nf++) {
                const int col = nw * (NF * 8) + nf * 8 + tg * 2;
                if (r0 < NN) {
                    __half2 h = __floats2half2_rn(acc[mf][nf][0], acc[mf][nf][1]);
                    *reinterpret_cast<__half2*>(&g_G[(size_t)r0 * OUTD + col]) = h;
                }
                if (r0 + 8 < NN) {
                    __half2 h = __floats2half2_rn(acc[mf][nf][2], acc[mf][nf][3]);
                    *reinterpret_cast<__half2*>(&g_G[(size_t)(r0 + 8) * OUTD + col]) = h;
                }
            }
        }
    }
}

// ---------------- CSR gather aggregation: half-warp per node, predicated batch-8 ----------------
// WIDTH=128: 16 lanes x uint4 (8 halfs) covers a 256B row.  H[n] = relu(sum*ni + b)*no -> fp16
// WIDTH=64 : 16 lanes x uint2 (4 halfs) covers a 128B row.  out[n] = sum*ni + b -> fp32
template <int WIDTH, bool FINAL>
__global__ void __launch_bounds__(256) agg_kernel(const float* __restrict__ bias,
                                                  float* __restrict__ outp) {
    const int l   = threadIdx.x & 15;                                   // lane in half-warp
    const int ghw = (blockIdx.x * blockDim.x + threadIdx.x) >> 4;       // global half-warp
    const int nhw = (gridDim.x * blockDim.x) >> 4;

    for (int n = ghw; n < NN; n += nhw) {
        const int beg = g_off[n];
        const int deg = g_cnt[n];
        const int end = beg + deg;

        if (WIDTH == 128) {
            float accA[8] = {0,0,0,0,0,0,0,0};
            float accB[8] = {0,0,0,0,0,0,0,0};
            if (deg > 0) {
                for (int base = beg; base < end; base += 8) {
                    uint4 raw[8];
#pragma unroll
                    for (int m = 0; m < 8; m++) {
                        const int ee = base + m;
                        const bool valid = ee < end;
                        const int s = __ldg(&g_csr_src[valid ? ee : beg]);
                        uint4 r = reinterpret_cast<const uint4*>(g_G + (size_t)s * 128)[l];
                        raw[m].x = valid ? r.x : 0u;
                        raw[m].y = valid ? r.y : 0u;
                        raw[m].z = valid ? r.z : 0u;
                        raw[m].w = valid ? r.w : 0u;
                    }
#pragma unroll
                    for (int m = 0; m < 8; m++) {
                        float* acc = (m & 1) ? accB : accA;
                        const float2 p0 = __half22float2(*reinterpret_cast<const __half2*>(&raw[m].x));
                        const float2 p1 = __half22float2(*reinterpret_cast<const __half2*>(&raw[m].y));
                        const float2 p2 = __half22float2(*reinterpret_cast<const __half2*>(&raw[m].z));
                        const float2 p3 = __half22float2(*reinterpret_cast<const __half2*>(&raw[m].w));
                        acc[0] += p0.x; acc[1] += p0.y; acc[2] += p1.x; acc[3] += p1.y;
                        acc[4] += p2.x; acc[5] += p2.y; acc[6] += p3.x; acc[7] += p3.y;
                    }
                }
            }
            const float ni = g_norm_in[n];
            const float no = g_norm_out[n];
            const float4 bb0 = reinterpret_cast<const float4*>(bias)[l * 2];
            const float4 bb1 = reinterpret_cast<const float4*>(bias)[l * 2 + 1];
            float r0 = fmaxf(fmaf(accA[0] + accB[0], ni, bb0.x), 0.f) * no;
            float r1 = fmaxf(fmaf(accA[1] + accB[1], ni, bb0.y), 0.f) * no;
            float r2 = fmaxf(fmaf(accA[2] + accB[2], ni, bb0.z), 0.f) * no;
            float r3 = fmaxf(fmaf(accA[3] + accB[3], ni, bb0.w), 0.f) * no;
            float r4 = fmaxf(fmaf(accA[4] + accB[4], ni, bb1.x), 0.f) * no;
            float r5 = fmaxf(fmaf(accA[5] + accB[5], ni, bb1.y), 0.f) * no;
            float r6 = fmaxf(fmaf(accA[6] + accB[6], ni, bb1.z), 0.f) * no;
            float r7 = fmaxf(fmaf(accA[7] + accB[7], ni, bb1.w), 0.f) * no;
            __half2 h0 = __floats2half2_rn(r0, r1);
            __half2 h1 = __floats2half2_rn(r2, r3);
            __half2 h2 = __floats2half2_rn(r4, r5);
            __half2 h3 = __floats2half2_rn(r6, r7);
            uint4 o;
            o.x = *reinterpret_cast<uint32_t*>(&h0);
            o.y = *reinterpret_cast<uint32_t*>(&h1);
            o.z = *reinterpret_cast<uint32_t*>(&h2);
            o.w = *reinterpret_cast<uint32_t*>(&h3);
            reinterpret_cast<uint4*>(g_H + (size_t)n * 128)[l] = o;
        } else {
            float accA[4] = {0,0,0,0};
            float accB[4] = {0,0,0,0};
            if (deg > 0) {
                for (int base = beg; base < end; base += 8) {
                    uint2 raw[8];
#pragma unroll
                    for (int m = 0; m < 8; m++) {
                        const int ee = base + m;
                        const bool valid = ee < end;
                        const int s = __ldg(&g_csr_src[valid ? ee : beg]);
                        uint2 r = reinterpret_cast<const uint2*>(g_G + (size_t)s * 64)[l];
                        raw[m].x = valid ? r.x : 0u;
                        raw[m].y = valid ? r.y : 0u;
                    }
#pragma unroll
                    for (int m = 0; m < 8; m++) {
                        float* acc = (m & 1) ? accB : accA;
                        const float2 p0 = __half22float2(*reinterpret_cast<const __half2*>(&raw[m].x));
                        const float2 p1 = __half22float2(*reinterpret_cast<const __half2*>(&raw[m].y));
                        acc[0] += p0.x; acc[1] += p0.y; acc[2] += p1.x; acc[3] += p1.y;
                    }
                }
            }
            const float ni = g_norm_in[n];
            const float4 bb = reinterpret_cast<const float4*>(bias)[l];
            float4 o;
            o.x = fmaf(accA[0] + accB[0], ni, bb.x);
            o.y = fmaf(accA[1] + accB[1], ni, bb.y);
            o.z = fmaf(accA[2] + accB[2], ni, bb.z);
            o.w = fmaf(accA[3] + accB[3], ni, bb.w);
            reinterpret_cast<float4*>(outp + (size_t)n * 64)[l] = o;
        }
    }
}

// ---------------- launch ----------------
extern "C" void kernel_launch(void* const* d_in, const int* in_sizes, int n_in,
                              void* d_out, int out_size) {
    const float* feat = (const float*)d_in[0];
    const int*   src  = (const int*)d_in[1];
    const int*   dst  = (const int*)d_in[2];
    const float* W0   = (const float*)d_in[3];
    const float* b0   = (const float*)d_in[4];
    const float* W1   = (const float*)d_in[5];
    const float* b1   = (const float*)d_in[6];
    const float* W2   = (const float*)d_in[7];
    const float* b2   = (const float*)d_in[8];
    float* out = (float*)d_out;

    const int SM128 = (128 * 68 + 64 * 68) * 4;  // 52224 B
    const int SM64  = (64 * 68 + 64 * 68) * 4;   // 34816 B
    cudaFuncSetAttribute(mma_gemm<128, false>, cudaFuncAttributeMaxDynamicSharedMemorySize, SM128);
    cudaFuncSetAttribute(mma_gemm<128, true>,  cudaFuncAttributeMaxDynamicSharedMemorySize, SM128);
    cudaFuncSetAttribute(mma_gemm<64,  true>,  cudaFuncAttributeMaxDynamicSharedMemorySize, SM64);

    const int T = 256;
    const int GGRID = 444;   // 3 CTAs/SM
    const int AGRID = 1184;

    // CSR build + norms
    zero_kernel<<<(NN + T - 1) / T, T>>>();
    hist_kernel<<<(NE + T - 1) / T, T>>>(src, dst);
    scan1_kernel<<<NBLK_SCAN, 256>>>();
    scan2_kernel<<<1, 256>>>();
    scan3_kernel<<<(NN + T - 1) / T, T>>>();
    place_kernel<<<(NE + T - 1) / T, T>>>(src, dst);

    // layer 0
    mma_gemm<128, false><<<GGRID, T, SM128>>>(feat, W0);
    agg_kernel<128, false><<<AGRID, T>>>(b0, nullptr);

    // layer 1
    mma_gemm<128, true><<<GGRID, T, SM128>>>(nullptr, W1);
    agg_kernel<128, false><<<AGRID, T>>>(b1, nullptr);

    // layer 2 (64-wide)
    mma_gemm<64, true><<<GGRID, T, SM64>>>(nullptr, W2);
    agg_kernel<64, true><<<AGRID, T>>>(b2, out);
}

// round 9
// speedup vs baseline: 3.4596x; 1.0641x over previous
#include <cuda_runtime.h>
#include <cuda_fp16.h>
#include <cstdint>
#include <cstddef>

#define NN 170000
#define NE 1200000
#define NBLK_SCAN 167   // ceil(NN / 1024)

// ---------------- device scratch (allocation-free) ----------------
__device__ __half g_G[(size_t)NN * 128];  // GEMM output (fp16)
__device__ __half g_H[(size_t)NN * 128];  // post-aggregation features (fp16)
__device__ int    g_deg_out[NN];
__device__ int    g_cnt[NN];
__device__ int    g_off[NN];
__device__ int    g_fill[NN];
__device__ int    g_bsum[NBLK_SCAN];
__device__ float  g_norm_out[NN];
__device__ float  g_norm_in[NN];
__device__ int    g_csr_src[NE];

// ---------------- CSR build ----------------
__global__ void zero_kernel() {
    int i = blockIdx.x * blockDim.x + threadIdx.x;
    if (i < NN) { g_deg_out[i] = 0; g_cnt[i] = 0; g_fill[i] = 0; }
}

__global__ void hist_kernel(const int* __restrict__ src, const int* __restrict__ dst) {
    int e = blockIdx.x * blockDim.x + threadIdx.x;
    if (e < NE) {
        atomicAdd(&g_deg_out[src[e]], 1);
        atomicAdd(&g_cnt[dst[e]], 1);
    }
}

__global__ void norm_kernel() {   // norms only (launch #3, so GEMM0 can run as #4)
    int i = blockIdx.x * blockDim.x + threadIdx.x;
    if (i < NN) {
        int din  = g_cnt[i];     if (din  < 1) din  = 1;
        int dout = g_deg_out[i]; if (dout < 1) dout = 1;
        g_norm_in[i]  = rsqrtf((float)din);
        g_norm_out[i] = rsqrtf((float)dout);
    }
}

__global__ void scan1_kernel() {
    __shared__ int sh[256];
    const int t = threadIdx.x;
    const int base = blockIdx.x * 1024 + t * 4;
    int c0 = 0, c1 = 0, c2 = 0, c3 = 0;
    if (base + 3 < NN) {
        int4 v = *reinterpret_cast<const int4*>(&g_cnt[base]);
        c0 = v.x; c1 = v.y; c2 = v.z; c3 = v.w;
    } else {
        if (base     < NN) c0 = g_cnt[base];
        if (base + 1 < NN) c1 = g_cnt[base + 1];
        if (base + 2 < NN) c2 = g_cnt[base + 2];
        if (base + 3 < NN) c3 = g_cnt[base + 3];
    }
    const int mysum = c0 + c1 + c2 + c3;
    sh[t] = mysum;
    __syncthreads();
    for (int off = 1; off < 256; off <<= 1) {
        int v = (t >= off) ? sh[t - off] : 0;
        __syncthreads();
        sh[t] += v;
        __syncthreads();
    }
    const int excl = sh[t] - mysum;
    if (t == 255) g_bsum[blockIdx.x] = sh[255];
    if (base     < NN) g_off[base]     = excl;
    if (base + 1 < NN) g_off[base + 1] = excl + c0;
    if (base + 2 < NN) g_off[base + 2] = excl + c0 + c1;
    if (base + 3 < NN) g_off[base + 3] = excl + c0 + c1 + c2;
}

__global__ void scan2_kernel() {
    __shared__ int sh[256];
    const int t = threadIdx.x;
    int v = (t < NBLK_SCAN) ? g_bsum[t] : 0;
    sh[t] = v;
    __syncthreads();
    for (int off = 1; off < 256; off <<= 1) {
        int u = (t >= off) ? sh[t - off] : 0;
        __syncthreads();
        sh[t] += u;
        __syncthreads();
    }
    if (t < NBLK_SCAN) g_bsum[t] = sh[t] - v;
}

__global__ void scan3_kernel() {   // offsets only
    int i = blockIdx.x * blockDim.x + threadIdx.x;
    if (i < NN) g_off[i] += g_bsum[i >> 10];
}

__global__ void place_kernel(const int* __restrict__ src, const int* __restrict__ dst) {
    int e = blockIdx.x * blockDim.x + threadIdx.x;
    if (e < NE) {
        const int d = dst[e];
        const int pos = g_off[d] + atomicAdd(&g_fill[d], 1);
        g_csr_src[pos] = src[e];
    }
}

// ---------------- mma / ldmatrix helpers ----------------
__device__ __forceinline__ void mma_f16(float* c, const uint32_t* a, uint32_t b0, uint32_t b1) {
    asm volatile(
        "mma.sync.aligned.m16n8k16.row.col.f32.f16.f16.f32 "
        "{%0,%1,%2,%3}, {%4,%5,%6,%7}, {%8,%9}, {%0,%1,%2,%3};"
        : "+f"(c[0]), "+f"(c[1]), "+f"(c[2]), "+f"(c[3])
        : "r"(a[0]), "r"(a[1]), "r"(a[2]), "r"(a[3]), "r"(b0), "r"(b1));
}

__device__ __forceinline__ void ldsm_x4(uint32_t* r, uint32_t addr) {
    asm volatile("ldmatrix.sync.aligned.m8n8.x4.shared.b16 {%0,%1,%2,%3}, [%4];"
                 : "=r"(r[0]), "=r"(r[1]), "=r"(r[2]), "=r"(r[3]) : "r"(addr));
}

__device__ __forceinline__ void ldsm_x2(uint32_t& r0, uint32_t& r1, uint32_t addr) {
    asm volatile("ldmatrix.sync.aligned.m8n8.x2.shared.b16 {%0,%1}, [%2];"
                 : "=r"(r0), "=r"(r1) : "r"(addr));
}

// ---------------- tensor-core GEMM (fp16 m16n8k16 + ldmatrix): G = f(X) @ W ----------------
// Smem layout: 32-bit words (2 halfs along k), row stride P=68 words.
// ldmatrix bank check: row base bank = 4*row mod 32; 8 address lanes x 16B spans cover
// all 32 banks exactly once -> conflict-free.
template <int OUTD, bool SRC_H>
__global__ void __launch_bounds__(256, 3) mma_gemm(const float* __restrict__ X,
                                                   const float* __restrict__ W) {
    constexpr int NF = OUTD / 32;
    constexpr int P  = 68;
    extern __shared__ uint32_t smw[];
    uint32_t* Wh = smw;                    // [OUTD][P]
    uint32_t* Ah = Wh + OUTD * P;          // [64][P]

    const int tid  = threadIdx.x;
    const int lane = tid & 31;
    const int warp = tid >> 5;
    const int mw   = warp & 1;
    const int nw   = warp >> 1;
    const int g    = lane >> 2;
    const int tg   = lane & 3;

    // W -> smem, transposed [n][k], fp16 pairs
    for (int i = tid; i < 64 * OUTD; i += 256) {
        const int kp = i / OUTD, n = i - kp * OUTD;
        const float w0 = W[(size_t)(kp * 2)     * OUTD + n];
        const float w1 = W[(size_t)(kp * 2 + 1) * OUTD + n];
        __half2 h = __floats2half2_rn(w0, w1);
        Wh[n * P + kp] = *reinterpret_cast<uint32_t*>(&h);
    }

    // ldmatrix per-lane base addresses
    const uint32_t aBase = (uint32_t)__cvta_generic_to_shared(Ah);
    const uint32_t wBase = (uint32_t)__cvta_generic_to_shared(Wh);
    const int sel = lane >> 3;      // 0..3
    const int li  = lane & 7;       // 0..7
    uint32_t aAddr[2];
#pragma unroll
    for (int mf = 0; mf < 2; mf++) {
        const int row = mw * 32 + mf * 16 + (sel & 1) * 8 + li;
        const int kw0 = (sel >> 1) * 4;
        aAddr[mf] = aBase + (row * P + kw0) * 4;
    }
    uint32_t bAddr[NF];
#pragma unroll
    for (int nf = 0; nf < NF; nf++) {
        const int n   = nw * (NF * 8) + nf * 8 + li;
        const int kw0 = (sel & 1) * 4;   // lanes 0-15 used by x2; 16-31 valid dummies
        bAddr[nf] = wBase + (n * P + kw0) * 4;
    }

    const int ntiles = (NN + 63) / 64;
    for (int tile = blockIdx.x; tile < ntiles; tile += gridDim.x) {
        __syncthreads();
        const int rowbase = tile * 64;

        for (int i = tid; i < 64 * 32; i += 256) {
            const int r = i >> 5, c4 = i & 31;
            const int row = rowbase + r;
            uint32_t w0 = 0, w1 = 0;
            if (row < NN) {
                if (SRC_H) {
                    const uint2 raw = reinterpret_cast<const uint2*>(g_H + (size_t)row * 128)[c4];
                    w0 = raw.x; w1 = raw.y;
                } else {
                    float4 v = reinterpret_cast<const float4*>(X + (size_t)row * 128)[c4];
                    const float no = g_norm_out[row];
                    __half2 h0 = __floats2half2_rn(v.x * no, v.y * no);
                    __half2 h1 = __floats2half2_rn(v.z * no, v.w * no);
                    w0 = *reinterpret_cast<uint32_t*>(&h0);
                    w1 = *reinterpret_cast<uint32_t*>(&h1);
                }
            }
            Ah[r * P + c4 * 2]     = w0;
            Ah[r * P + c4 * 2 + 1] = w1;
        }
        __syncthreads();

        float acc[2][NF][4];
#pragma unroll
        for (int mf = 0; mf < 2; mf++)
#pragma unroll
            for (int nf = 0; nf < NF; nf++)
#pragma unroll
                for (int j = 0; j < 4; j++) acc[mf][nf][j] = 0.f;

#pragma unroll
        for (int ks = 0; ks < 8; ks++) {
            uint32_t a[2][4];
            ldsm_x4(a[0], aAddr[0] + ks * 32);
            ldsm_x4(a[1], aAddr[1] + ks * 32);
            uint32_t b[NF][2];
#pragma unroll
            for (int nf = 0; nf < NF; nf++)
                ldsm_x2(b[nf][0], b[nf][1], bAddr[nf] + ks * 32);
#pragma unroll
            for (int nf = 0; nf < NF; nf++)
#pragma unroll
                for (int mf = 0; mf < 2; mf++)
                    mma_f16(acc[mf][nf], a[mf], b[nf][0], b[nf][1]);
        }

#pragma unroll
        for (int mf = 0; mf < 2; mf++) {
            const int r0 = rowbase + mw * 32 + mf * 16 + g;
#pragma unroll
            for (int nf = 0; nf < NF; nf++) {
                const int col = nw * (NF * 8) + nf * 8 + tg * 2;
                if (r0 < NN) {
                    __half2 h = __floats2half2_rn(acc[mf][nf][0], acc[mf][nf][1]);
                    *reinterpret_cast<__half2*>(&g_G[(size_t)r0 * OUTD + col]) = h;
                }
                if (r0 + 8 < NN) {
                    __half2 h = __floats2half2_rn(acc[mf][nf][2], acc[mf][nf][3]);
                    *reinterpret_cast<__half2*>(&g_G[(size_t)(r0 + 8) * OUTD + col]) = h;
                }
            }
        }
    }
}

// ---------------- CSR gather aggregation: half-warp per node ----------------
// Full batches of 8 unpredicated; single predicated tail batch.
template <int WIDTH, bool FINAL>
__global__ void __launch_bounds__(256) agg_kernel(const float* __restrict__ bias,
                                                  float* __restrict__ outp) {
    const int l   = threadIdx.x & 15;
    const int ghw = (blockIdx.x * blockDim.x + threadIdx.x) >> 4;
    const int nhw = (gridDim.x * blockDim.x) >> 4;

    for (int n = ghw; n < NN; n += nhw) {
        const int beg = g_off[n];
        const int deg = g_cnt[n];
        const int end = beg + deg;

        if (WIDTH == 128) {
            float accA[8] = {0,0,0,0,0,0,0,0};
            float accB[8] = {0,0,0,0,0,0,0,0};
            int e = beg;
            for (; e + 8 <= end; e += 8) {
                uint4 raw[8];
#pragma unroll
                for (int m = 0; m < 8; m++) {
                    const int s = __ldg(&g_csr_src[e + m]);
                    raw[m] = reinterpret_cast<const uint4*>(g_G + (size_t)s * 128)[l];
                }
#pragma unroll
                for (int m = 0; m < 8; m++) {
                    float* acc = (m & 1) ? accB : accA;
                    const float2 p0 = __half22float2(*reinterpret_cast<const __half2*>(&raw[m].x));
                    const float2 p1 = __half22float2(*reinterpret_cast<const __half2*>(&raw[m].y));
                    const float2 p2 = __half22float2(*reinterpret_cast<const __half2*>(&raw[m].z));
                    const float2 p3 = __half22float2(*reinterpret_cast<const __half2*>(&raw[m].w));
                    acc[0] += p0.x; acc[1] += p0.y; acc[2] += p1.x; acc[3] += p1.y;
                    acc[4] += p2.x; acc[5] += p2.y; acc[6] += p3.x; acc[7] += p3.y;
                }
            }
            if (e < end) {
                uint4 raw[8];
#pragma unroll
                for (int m = 0; m < 8; m++) {
                    const int ee = e + m;
                    const bool valid = ee < end;
                    const int s = __ldg(&g_csr_src[valid ? ee : beg]);
                    uint4 r = reinterpret_cast<const uint4*>(g_G + (size_t)s * 128)[l];
                    raw[m].x = valid ? r.x : 0u;
                    raw[m].y = valid ? r.y : 0u;
                    raw[m].z = valid ? r.z : 0u;
                    raw[m].w = valid ? r.w : 0u;
                }
#pragma unroll
                for (int m = 0; m < 8; m++) {
                    float* acc = (m & 1) ? accB : accA;
                    const float2 p0 = __half22float2(*reinterpret_cast<const __half2*>(&raw[m].x));
                    const float2 p1 = __half22float2(*reinterpret_cast<const __half2*>(&raw[m].y));
                    const float2 p2 = __half22float2(*reinterpret_cast<const __half2*>(&raw[m].z));
                    const float2 p3 = __half22float2(*reinterpret_cast<const __half2*>(&raw[m].w));
                    acc[0] += p0.x; acc[1] += p0.y; acc[2] += p1.x; acc[3] += p1.y;
                    acc[4] += p2.x; acc[5] += p2.y; acc[6] += p3.x; acc[7] += p3.y;
                }
            }
            const float ni = g_norm_in[n];
            const float no = g_norm_out[n];
            const float4 bb0 = reinterpret_cast<const float4*>(bias)[l * 2];
            const float4 bb1 = reinterpret_cast<const float4*>(bias)[l * 2 + 1];
            float r0 = fmaxf(fmaf(accA[0] + accB[0], ni, bb0.x), 0.f) * no;
            float r1 = fmaxf(fmaf(accA[1] + accB[1], ni, bb0.y), 0.f) * no;
            float r2 = fmaxf(fmaf(accA[2] + accB[2], ni, bb0.z), 0.f) * no;
            float r3 = fmaxf(fmaf(accA[3] + accB[3], ni, bb0.w), 0.f) * no;
            float r4 = fmaxf(fmaf(accA[4] + accB[4], ni, bb1.x), 0.f) * no;
            float r5 = fmaxf(fmaf(accA[5] + accB[5], ni, bb1.y), 0.f) * no;
            float r6 = fmaxf(fmaf(accA[6] + accB[6], ni, bb1.z), 0.f) * no;
            float r7 = fmaxf(fmaf(accA[7] + accB[7], ni, bb1.w), 0.f) * no;
            __half2 h0 = __floats2half2_rn(r0, r1);
            __half2 h1 = __floats2half2_rn(r2, r3);
            __half2 h2 = __floats2half2_rn(r4, r5);
            __half2 h3 = __floats2half2_rn(r6, r7);
            uint4 o;
            o.x = *reinterpret_cast<uint32_t*>(&h0);
            o.y = *reinterpret_cast<uint32_t*>(&h1);
            o.z = *reinterpret_cast<uint32_t*>(&h2);
            o.w = *reinterpret_cast<uint32_t*>(&h3);
            reinterpret_cast<uint4*>(g_H + (size_t)n * 128)[l] = o;
        } else {
            float accA[4] = {0,0,0,0};
            float accB[4] = {0,0,0,0};
            int e = beg;
            for (; e + 8 <= end; e += 8) {
                uint2 raw[8];
#pragma unroll
                for (int m = 0; m < 8; m++) {
                    const int s = __ldg(&g_csr_src[e + m]);
                    raw[m] = reinterpret_cast<const uint2*>(g_G + (size_t)s * 64)[l];
                }
#pragma unroll
                for (int m = 0; m < 8; m++) {
                    float* acc = (m & 1) ? accB : accA;
                    const float2 p0 = __half22float2(*reinterpret_cast<const __half2*>(&raw[m].x));
                    const float2 p1 = __half22float2(*reinterpret_cast<const __half2*>(&raw[m].y));
                    acc[0] += p0.x; acc[1] += p0.y; acc[2] += p1.x; acc[3] += p1.y;
                }
            }
            if (e < end) {
                uint2 raw[8];
#pragma unroll
                for (int m = 0; m < 8; m++) {
                    const int ee = e + m;
                    const bool valid = ee < end;
                    const int s = __ldg(&g_csr_src[valid ? ee : beg]);
                    uint2 r = reinterpret_cast<const uint2*>(g_G + (size_t)s * 64)[l];
                    raw[m].x = valid ? r.x : 0u;
                    raw[m].y = valid ? r.y : 0u;
                }
#pragma unroll
                for (int m = 0; m < 8; m++) {
                    float* acc = (m & 1) ? accB : accA;
                    const float2 p0 = __half22float2(*reinterpret_cast<const __half2*>(&raw[m].x));
                    const float2 p1 = __half22float2(*reinterpret_cast<const __half2*>(&raw[m].y));
                    acc[0] += p0.x; acc[1] += p0.y; acc[2] += p1.x; acc[3] += p1.y;
                }
            }
            const float ni = g_norm_in[n];
            const float4 bb = reinterpret_cast<const float4*>(bias)[l];
            float4 o;
            o.x = fmaf(accA[0] + accB[0], ni, bb.x);
            o.y = fmaf(accA[1] + accB[1], ni, bb.y);
            o.z = fmaf(accA[2] + accB[2], ni, bb.z);
            o.w = fmaf(accA[3] + accB[3], ni, bb.w);
            reinterpret_cast<float4*>(outp + (size_t)n * 64)[l] = o;
        }
    }
}

// ---------------- launch ----------------
extern "C" void kernel_launch(void* const* d_in, const int* in_sizes, int n_in,
                              void* d_out, int out_size) {
    const float* feat = (const float*)d_in[0];
    const int*   src  = (const int*)d_in[1];
    const int*   dst  = (const int*)d_in[2];
    const float* W0   = (const float*)d_in[3];
    const float* b0   = (const float*)d_in[4];
    const float* W1   = (const float*)d_in[5];
    const float* b1   = (const float*)d_in[6];
    const float* W2   = (const float*)d_in[7];
    const float* b2   = (const float*)d_in[8];
    float* out = (float*)d_out;

    const int SM128 = (128 * 68 + 64 * 68) * 4;  // 52224 B
    const int SM64  = (64 * 68 + 64 * 68) * 4;   // 34816 B
    cudaFuncSetAttribute(mma_gemm<128, false>, cudaFuncAttributeMaxDynamicSharedMemorySize, SM128);
    cudaFuncSetAttribute(mma_gemm<128, true>,  cudaFuncAttributeMaxDynamicSharedMemorySize, SM128);
    cudaFuncSetAttribute(mma_gemm<64,  true>,  cudaFuncAttributeMaxDynamicSharedMemorySize, SM64);

    const int T = 256;
    const int GGRID = 444;   // 3 CTAs/SM
    const int AGRID = 1184;

    // 1-2: degree histogram
    zero_kernel<<<(NN + T - 1) / T, T>>>();
    hist_kernel<<<(NE + T - 1) / T, T>>>(src, dst);
    // 3: norms (GEMM0 only needs norm_out)
    norm_kernel<<<(NN + T - 1) / T, T>>>();
    // 4: layer-0 GEMM (profiled slot)
    mma_gemm<128, false><<<GGRID, T, SM128>>>(feat, W0);
    // 5-8: CSR offsets + placement
    scan1_kernel<<<NBLK_SCAN, 256>>>();
    scan2_kernel<<<1, 256>>>();
    scan3_kernel<<<(NN + T - 1) / T, T>>>();
    place_kernel<<<(NE + T - 1) / T, T>>>(src, dst);

    // layer 0 aggregation
    agg_kernel<128, false><<<AGRID, T>>>(b0, nullptr);

    // layer 1
    mma_gemm<128, true><<<GGRID, T, SM128>>>(nullptr, W1);
    agg_kernel<128, false><<<AGRID, T>>>(b1, nullptr);

    // layer 2 (64-wide)
    mma_gemm<64, true><<<GGRID, T, SM64>>>(nullptr, W2);
    agg_kernel<64, true><<<AGRID, T>>>(b2, out);
}